// round 10
// baseline (speedup 1.0000x reference)
#include <cuda_runtime.h>
#include <cstdint>

// ---------------- static scratch (allocation-free rule) ----------------
#define NSEG 100000
#define NROWS_MAX 2000000

__device__ __align__(16) float g_H[(size_t)NROWS_MAX * 64];      // 512 MB
__device__ __align__(16) float g_agg[3u * NSEG * 64];            // 76.8 MB (L2-hot)
__device__ __align__(16) float g_G[(size_t)NSEG * 64];           // 25.6 MB (L2-hot)
__device__ int   g_cnt[NSEG];
__device__ float g_colsq[128];
__device__ float g_inv[128];
__device__ int   g_is64;

// ---------------- f32x2 packed-math helpers (sm_103a) ----------------
__device__ __forceinline__ unsigned long long pack2(float a, float b) {
    unsigned long long r;
    asm("mov.b64 %0, {%1, %2};" : "=l"(r) : "f"(a), "f"(b));
    return r;
}
__device__ __forceinline__ unsigned long long ffma2(unsigned long long a,
                                                    unsigned long long b,
                                                    unsigned long long c) {
    unsigned long long d;
    asm("fma.rn.f32x2 %0, %1, %2, %3;" : "=l"(d) : "l"(a), "l"(b), "l"(c));
    return d;
}
__device__ __forceinline__ void unpack2(unsigned long long v, float& a, float& b) {
    asm("mov.b64 {%0, %1}, %2;" : "=f"(a), "=f"(b) : "l"(v));
}

__device__ __forceinline__ int get_cat(const void* cat, int i, int is64) {
    if (is64) return (int)((const long long*)cat)[i];
    return ((const int*)cat)[i];
}

// filtered float atomicMax for non-negative floats (uint monotone)
__device__ __forceinline__ void agg_max(float* p, float h, float cur) {
    if (h > cur) atomicMax((unsigned int*)p, __float_as_uint(h));
}

// ---------------- kernels ----------------

// init + dtype detect fused (keeps k_layer<false> at launch index 4 for ncu)
__global__ void k_init(const unsigned int* cat) {
    int i = blockIdx.x * blockDim.x + threadIdx.x;
    if (blockIdx.x == 0 && threadIdx.x == 0) {
        int is64 = 1;
        for (int t = 0; t < 64; t++)
            if (cat[2 * t + 1] != 0u) { is64 = 0; break; }
        g_is64 = is64;
    }
    int stride = gridDim.x * blockDim.x;
    float4 z = make_float4(0.f, 0.f, 0.f, 0.f);
    float4* a4 = (float4*)g_agg;
    const int T4 = 3 * NSEG * 64 / 4;
    for (int j = i; j < T4; j += stride) a4[j] = z;
    for (int j = i; j < NSEG; j += stride) g_cnt[j] = 0;
    if (i < 128) g_colsq[i] = 0.f;
}

// ---------------- Layer 0 (tiled, low-reg, 4 CTAs/SM) ----------------
#define L0_XS_BYTES (128 * 8 * 4)        // 4096
#define L0_WS_BYTES (8 * 64 * 4)         // 2048
#define L0_CATS_OFF (L0_XS_BYTES + L0_WS_BYTES)
#define L0_SMEM     (L0_CATS_OFF + 512)

__global__ __launch_bounds__(256, 4) void k_layer0(
    const float* __restrict__ x, const void* __restrict__ cat,
    const float* __restrict__ W, const float* __restrict__ bia,
    const float* __restrict__ gam, const float* __restrict__ bet, int N)
{
    extern __shared__ char smem[];
    float* Xs = (float*)smem;                                   // [128][8]
    const ulonglong2* Wsp = (const ulonglong2*)(smem + L0_XS_BYTES); // [8][16]
    int* cats = (int*)(smem + L0_CATS_OFF);

    int tid = threadIdx.x;
    int base = blockIdx.x * 128;
    int is64 = g_is64;

    if (tid < 128) {
        int r = base + tid;
        int c = (r < N) ? get_cat(cat, r, is64) : 0;
        cats[tid] = c;
        if (r < N) atomicAdd(&g_cnt[c], 1);
    }
    if (tid < 128) {
        ((float4*)(smem + L0_XS_BYTES))[tid] = ((const float4*)W)[tid];
    }
    {
        int r = tid >> 1, c4 = tid & 1;
        int rg = base + r;
        float4 v = make_float4(0.f, 0.f, 0.f, 0.f);
        if (rg < N) v = ((const float4*)x)[(size_t)rg * 2 + c4];
        ((float4*)Xs)[tid] = v;
    }
    __syncthreads();

    int tx = tid & 15, tyg = tid >> 4;
    int r0 = tyg * 8;

    unsigned long long acc[8][2];
#pragma unroll
    for (int i = 0; i < 8; i++) { acc[i][0] = 0ull; acc[i][1] = 0ull; }

#pragma unroll
    for (int k4 = 0; k4 < 2; k4++) {
        ulonglong2 w0 = Wsp[(k4 * 4 + 0) * 16 + tx];
        ulonglong2 w1 = Wsp[(k4 * 4 + 1) * 16 + tx];
        ulonglong2 w2 = Wsp[(k4 * 4 + 2) * 16 + tx];
        ulonglong2 w3 = Wsp[(k4 * 4 + 3) * 16 + tx];
#pragma unroll
        for (int i = 0; i < 8; i++) {
            float4 xv = ((const float4*)(Xs + (r0 + i) * 8))[k4];
            unsigned long long d;
            d = pack2(xv.x, xv.x);
            acc[i][0] = ffma2(d, w0.x, acc[i][0]); acc[i][1] = ffma2(d, w0.y, acc[i][1]);
            d = pack2(xv.y, xv.y);
            acc[i][0] = ffma2(d, w1.x, acc[i][0]); acc[i][1] = ffma2(d, w1.y, acc[i][1]);
            d = pack2(xv.z, xv.z);
            acc[i][0] = ffma2(d, w2.x, acc[i][0]); acc[i][1] = ffma2(d, w2.y, acc[i][1]);
            d = pack2(xv.w, xv.w);
            acc[i][0] = ffma2(d, w3.x, acc[i][0]); acc[i][1] = ffma2(d, w3.y, acc[i][1]);
        }
    }

    int c0 = tx * 4;
    float4 bv  = *(const float4*)&bia[c0];
    float4 gv  = *(const float4*)&gam[c0];
    float4 bev = *(const float4*)&bet[c0];

    float* agg0 = g_agg;

#pragma unroll
    for (int i = 0; i < 8; i++) {
        int rg = base + r0 + i;
        int ci = cats[r0 + i];
        float4 cur = *(const float4*)(agg0 + (size_t)ci * 64 + c0);
        float a0, a1, a2, a3;
        unpack2(acc[i][0], a0, a1);
        unpack2(acc[i][1], a2, a3);
        a0 += bv.x; a1 += bv.y; a2 += bv.z; a3 += bv.w;
        float s1 = a0 + a1 + a2 + a3;
        float s2 = a0 * a0 + a1 * a1 + a2 * a2 + a3 * a3;
#pragma unroll
        for (int m = 1; m < 16; m <<= 1) {
            s1 += __shfl_xor_sync(0xffffffffu, s1, m);
            s2 += __shfl_xor_sync(0xffffffffu, s2, m);
        }
        float mean = s1 * (1.f / 64.f);
        float var  = s2 * (1.f / 64.f) - mean * mean;
        float rs   = rsqrtf(var + 1e-5f);
        float h0 = fmaxf(fmaf((a0 - mean) * rs, gv.x, bev.x), 0.f);
        float h1 = fmaxf(fmaf((a1 - mean) * rs, gv.y, bev.y), 0.f);
        float h2 = fmaxf(fmaf((a2 - mean) * rs, gv.z, bev.z), 0.f);
        float h3 = fmaxf(fmaf((a3 - mean) * rs, gv.w, bev.w), 0.f);
        if (rg < N) {
            ((float4*)&g_H[(size_t)rg * 64])[tx] = make_float4(h0, h1, h2, h3);
            float* ap = agg0 + (size_t)ci * 64 + c0;
            agg_max(ap + 0, h0, cur.x);
            agg_max(ap + 1, h1, cur.y);
            agg_max(ap + 2, h2, cur.z);
            agg_max(ap + 3, h3, cur.w);
        }
    }
}

// ---------------- G = agg @ W_bot  (per-segment precompute) ----------------
#define AMM_SMEM (128 * 64 * 4 + 64 * 64 * 4)   // 49152

__global__ __launch_bounds__(256, 3) void k_aggmm(int aggInIdx, const float* __restrict__ Wbot)
{
    extern __shared__ char smem[];
    float* As = (float*)smem;
    const ulonglong2* Wsp = (const ulonglong2*)(smem + 128 * 64 * 4);
    const float* agg = g_agg + (size_t)aggInIdx * NSEG * 64;

    int tid = threadIdx.x;
    int base = blockIdx.x * 128;

    {
        const float4* Wv = (const float4*)Wbot;
        float4* Wd = (float4*)(smem + 128 * 64 * 4);
#pragma unroll
        for (int t = 0; t < 4; t++) Wd[tid + t * 256] = Wv[tid + t * 256];
    }
    {
#pragma unroll
        for (int t = 0; t < 8; t++) {
            int idx = tid + t * 256;
            int r = idx >> 4, c4 = idx & 15;
            int rg = base + r;
            float4 v = make_float4(0.f, 0.f, 0.f, 0.f);
            if (rg < NSEG) v = ((const float4*)&agg[(size_t)rg * 64])[c4];
            ((float4*)&As[r * 64])[c4] = v;
        }
    }
    __syncthreads();

    int tx = tid & 15, tyg = tid >> 4;
    int r0 = tyg * 8;

    unsigned long long acc[8][2];
#pragma unroll
    for (int i = 0; i < 8; i++) { acc[i][0] = 0ull; acc[i][1] = 0ull; }

#pragma unroll 4
    for (int k4 = 0; k4 < 16; k4++) {
        ulonglong2 w0 = Wsp[(k4 * 4 + 0) * 16 + tx];
        ulonglong2 w1 = Wsp[(k4 * 4 + 1) * 16 + tx];
        ulonglong2 w2 = Wsp[(k4 * 4 + 2) * 16 + tx];
        ulonglong2 w3 = Wsp[(k4 * 4 + 3) * 16 + tx];
#pragma unroll
        for (int i = 0; i < 8; i++) {
            float4 xv = ((const float4*)(As + (r0 + i) * 64))[k4];
            unsigned long long d;
            d = pack2(xv.x, xv.x);
            acc[i][0] = ffma2(d, w0.x, acc[i][0]); acc[i][1] = ffma2(d, w0.y, acc[i][1]);
            d = pack2(xv.y, xv.y);
            acc[i][0] = ffma2(d, w1.x, acc[i][0]); acc[i][1] = ffma2(d, w1.y, acc[i][1]);
            d = pack2(xv.z, xv.z);
            acc[i][0] = ffma2(d, w2.x, acc[i][0]); acc[i][1] = ffma2(d, w2.y, acc[i][1]);
            d = pack2(xv.w, xv.w);
            acc[i][0] = ffma2(d, w3.x, acc[i][0]); acc[i][1] = ffma2(d, w3.y, acc[i][1]);
        }
    }

    int c0 = tx * 4;
#pragma unroll
    for (int i = 0; i < 8; i++) {
        int rg = base + r0 + i;
        if (rg < NSEG) {
            float a0, a1, a2, a3;
            unpack2(acc[i][0], a0, a1);
            unpack2(acc[i][1], a2, a3);
            *(float4*)&g_G[(size_t)rg * 64 + c0] = make_float4(a0, a1, a2, a3);
        }
    }
}

// ---------------- Layers 1/2 (row-in-one-warp tile, streaming epilogue) ----
// 256 threads; thread tile 4 rows x 8 cols.
//   txg = l & 7           (8 col-groups of 8; whole row within one warp)
//   tyg = w*4 | (l>>3)    (32 row-groups of 4)
// LN reduction = 3 shfl links over the 8 lanes sharing a row. No smem round trip.
// Xs chunk-swizzled: logical chunk c4 of row r stored at c4 ^ ((r>>2)&7).
// G[cat]+bias folded into acc init (gather before fill hides L2 latency).
#define XS_BYTES  (128 * 64 * 4)                 // 32768
#define WS_BYTES  (64 * 64 * 4)                  // 16384
#define CATS_OFF  (XS_BYTES + WS_BYTES)          // 49152
#define SCSQ_OFF  (CATS_OFF + 512)               // 49664
#define SMEM_BYTES (SCSQ_OFF + 256)              // 49920

template <bool COLSQ>
__global__ __launch_bounds__(256, 4) void k_layer(
    const void* __restrict__ cat, int aggOutIdx,
    const float* __restrict__ Wtop, const float* __restrict__ bia,
    const float* __restrict__ gam, const float* __restrict__ bet, int N)
{
    extern __shared__ char smem[];
    float* Xs = (float*)smem;                                  // [128][64] swizzled
    const float* Ws = (const float*)(smem + XS_BYTES);         // [64][64]
    int* cats = (int*)(smem + CATS_OFF);
    float* scolsq = (float*)(smem + SCSQ_OFF);

    float* aggOut = g_agg + (size_t)aggOutIdx * NSEG * 64;

    int tid = threadIdx.x;
    int base = blockIdx.x * 128;
    int is64 = g_is64;
    int w_ = tid >> 5, l = tid & 31;

    if (tid < 128) {
        int r = base + tid;
        cats[tid] = (r < N) ? get_cat(cat, r, is64) : 0;
    }
    __syncthreads();   // cats visible early

    int txg = l & 7;                 // 0..7
    int tyg = (w_ << 2) | (l >> 3);  // 0..31
    int r0 = tyg * 4;
    int c0 = txg * 8;

    // G[cat] prefetch: issued before the tile fill so the fill hides the L2 latency
    float4 gA[4], gB[4];
#pragma unroll
    for (int i = 0; i < 4; i++) {
        const float* gp = &g_G[(size_t)cats[r0 + i] * 64 + c0];
        gA[i] = *(const float4*)gp;
        gB[i] = *(const float4*)(gp + 4);
    }

    {   // W_top: 1024 float4 (plain layout)
        const float4* Wv = (const float4*)Wtop;
        float4* Wd = (float4*)(smem + XS_BYTES);
#pragma unroll
        for (int t = 0; t < 4; t++) Wd[tid + t * 256] = Wv[tid + t * 256];
    }
    {   // Xs = H tile: 2048 float4, chunk-swizzled per row
#pragma unroll
        for (int t = 0; t < 8; t++) {
            int idx = tid + t * 256;
            int r = idx >> 4, c4 = idx & 15;
            int rg = base + r;
            float4 v = make_float4(0.f, 0.f, 0.f, 0.f);
            if (rg < N) v = ((const float4*)&g_H[(size_t)rg * 64])[c4];
            ((float4*)Xs)[r * 16 + (c4 ^ ((r >> 2) & 7))] = v;
        }
    }
    __syncthreads();

    // acc init = G[cat] + bias (f32x2-packed)
    float4 biaA = *(const float4*)&bia[c0];
    float4 biaB = *(const float4*)&bia[c0 + 4];
    unsigned long long acc[4][4];
#pragma unroll
    for (int i = 0; i < 4; i++) {
        acc[i][0] = pack2(gA[i].x + biaA.x, gA[i].y + biaA.y);
        acc[i][1] = pack2(gA[i].z + biaA.z, gA[i].w + biaA.w);
        acc[i][2] = pack2(gB[i].x + biaB.x, gB[i].y + biaB.y);
        acc[i][3] = pack2(gB[i].z + biaB.z, gB[i].w + biaB.w);
    }

#define K4BODY(J, X0, X1, X2, X3) { \
    const float* wrow = Ws + (k4 * 4 + (J)) * 64 + c0; \
    ulonglong2 wA = *(const ulonglong2*)wrow; \
    ulonglong2 wB = *(const ulonglong2*)(wrow + 4); \
    unsigned long long d; \
    d = pack2(X0, X0); \
    acc[0][0] = ffma2(d, wA.x, acc[0][0]); acc[0][1] = ffma2(d, wA.y, acc[0][1]); \
    acc[0][2] = ffma2(d, wB.x, acc[0][2]); acc[0][3] = ffma2(d, wB.y, acc[0][3]); \
    d = pack2(X1, X1); \
    acc[1][0] = ffma2(d, wA.x, acc[1][0]); acc[1][1] = ffma2(d, wA.y, acc[1][1]); \
    acc[1][2] = ffma2(d, wB.x, acc[1][2]); acc[1][3] = ffma2(d, wB.y, acc[1][3]); \
    d = pack2(X2, X2); \
    acc[2][0] = ffma2(d, wA.x, acc[2][0]); acc[2][1] = ffma2(d, wA.y, acc[2][1]); \
    acc[2][2] = ffma2(d, wB.x, acc[2][2]); acc[2][3] = ffma2(d, wB.y, acc[2][3]); \
    d = pack2(X3, X3); \
    acc[3][0] = ffma2(d, wA.x, acc[3][0]); acc[3][1] = ffma2(d, wA.y, acc[3][1]); \
    acc[3][2] = ffma2(d, wB.x, acc[3][2]); acc[3][3] = ffma2(d, wB.y, acc[3][3]); \
}

#pragma unroll 4
    for (int k4 = 0; k4 < 16; k4++) {
        int chunk = k4 ^ (tyg & 7);
        float4 xv0 = ((const float4*)Xs)[(r0 + 0) * 16 + chunk];
        float4 xv1 = ((const float4*)Xs)[(r0 + 1) * 16 + chunk];
        float4 xv2 = ((const float4*)Xs)[(r0 + 2) * 16 + chunk];
        float4 xv3 = ((const float4*)Xs)[(r0 + 3) * 16 + chunk];
        K4BODY(0, xv0.x, xv1.x, xv2.x, xv3.x)
        K4BODY(1, xv0.y, xv1.y, xv2.y, xv3.y)
        K4BODY(2, xv0.z, xv1.z, xv2.z, xv3.z)
        K4BODY(3, xv0.w, xv1.w, xv2.w, xv3.w)
    }
#undef K4BODY

    // ---- streaming epilogue: one row at a time; row reduction = 3 shfl links ----
    float4 gvA = *(const float4*)&gam[c0];
    float4 gvB = *(const float4*)&gam[c0 + 4];
    float4 beA = *(const float4*)&bet[c0];
    float4 beB = *(const float4*)&bet[c0 + 4];
    float csq[8];
#pragma unroll
    for (int j = 0; j < 8; j++) csq[j] = 0.f;

#pragma unroll
    for (int i = 0; i < 4; i++) {
        float a0, a1, a2, a3, a4, a5, a6, a7;
        unpack2(acc[i][0], a0, a1);
        unpack2(acc[i][1], a2, a3);
        unpack2(acc[i][2], a4, a5);
        unpack2(acc[i][3], a6, a7);
        float s1 = ((a0 + a1) + (a2 + a3)) + ((a4 + a5) + (a6 + a7));
        float s2 = ((a0 * a0 + a1 * a1) + (a2 * a2 + a3 * a3))
                 + ((a4 * a4 + a5 * a5) + (a6 * a6 + a7 * a7));
        s1 += __shfl_xor_sync(0xffffffffu, s1, 1);
        s2 += __shfl_xor_sync(0xffffffffu, s2, 1);
        s1 += __shfl_xor_sync(0xffffffffu, s1, 2);
        s2 += __shfl_xor_sync(0xffffffffu, s2, 2);
        s1 += __shfl_xor_sync(0xffffffffu, s1, 4);
        s2 += __shfl_xor_sync(0xffffffffu, s2, 4);
        float mean = s1 * (1.f / 64.f);
        float var  = s2 * (1.f / 64.f) - mean * mean;
        float rs   = rsqrtf(var + 1e-5f);
        float h0 = fmaxf(fmaf((a0 - mean) * rs, gvA.x, beA.x), 0.f);
        float h1 = fmaxf(fmaf((a1 - mean) * rs, gvA.y, beA.y), 0.f);
        float h2 = fmaxf(fmaf((a2 - mean) * rs, gvA.z, beA.z), 0.f);
        float h3 = fmaxf(fmaf((a3 - mean) * rs, gvA.w, beA.w), 0.f);
        float h4 = fmaxf(fmaf((a4 - mean) * rs, gvB.x, beB.x), 0.f);
        float h5 = fmaxf(fmaf((a5 - mean) * rs, gvB.y, beB.y), 0.f);
        float h6 = fmaxf(fmaf((a6 - mean) * rs, gvB.z, beB.z), 0.f);
        float h7 = fmaxf(fmaf((a7 - mean) * rs, gvB.w, beB.w), 0.f);
        int rg = base + r0 + i;
        if (rg < N) {
            int ci = cats[r0 + i];
            float4* hp = (float4*)&g_H[(size_t)rg * 64 + c0];
            hp[0] = make_float4(h0, h1, h2, h3);
            hp[1] = make_float4(h4, h5, h6, h7);
            float* ap = aggOut + (size_t)ci * 64 + c0;
            float4 curA = *(const float4*)ap;
            float4 curB = *(const float4*)(ap + 4);
            agg_max(ap + 0, h0, curA.x);
            agg_max(ap + 1, h1, curA.y);
            agg_max(ap + 2, h2, curA.z);
            agg_max(ap + 3, h3, curA.w);
            agg_max(ap + 4, h4, curB.x);
            agg_max(ap + 5, h5, curB.y);
            agg_max(ap + 6, h6, curB.z);
            agg_max(ap + 7, h7, curB.w);
            if (COLSQ) {
                csq[0] = fmaf(h0, h0, csq[0]); csq[1] = fmaf(h1, h1, csq[1]);
                csq[2] = fmaf(h2, h2, csq[2]); csq[3] = fmaf(h3, h3, csq[3]);
                csq[4] = fmaf(h4, h4, csq[4]); csq[5] = fmaf(h5, h5, csq[5]);
                csq[6] = fmaf(h6, h6, csq[6]); csq[7] = fmaf(h7, h7, csq[7]);
            }
        }
    }
    if (COLSQ) {
        if (tid < 64) scolsq[tid] = 0.f;
        __syncthreads();
#pragma unroll
        for (int j = 0; j < 8; j++) atomicAdd(&scolsq[c0 + j], csq[j]);
        __syncthreads();
        if (tid < 64) atomicAdd(&g_colsq[tid], scolsq[tid]);
    }
}

// colsq for agg half: sum_s count[s] * agg2[s,j]^2  (L2-hot)
__global__ void k_aggsq(int aggIdx) {
    const float* agg = g_agg + (size_t)aggIdx * NSEG * 64;
    int j = threadIdx.x & 63;
    int sb_ = threadIdx.x >> 6;
    float acc = 0.f;
    for (int s = blockIdx.x * 4 + sb_; s < NSEG; s += gridDim.x * 4) {
        float cnt = (float)g_cnt[s];
        if (cnt > 0.f) {
            float v = agg[(size_t)s * 64 + j];
            acc = fmaf(cnt, v * v, acc);
        }
    }
    __shared__ float red[64];
    if (threadIdx.x < 64) red[threadIdx.x] = 0.f;
    __syncthreads();
    atomicAdd(&red[j], acc);
    __syncthreads();
    if (threadIdx.x < 64) atomicAdd(&g_colsq[64 + threadIdx.x], red[threadIdx.x]);
}

__global__ void k_inv() {
    int j = threadIdx.x;
    if (j < 128) g_inv[j] = 1.f / (sqrtf(g_colsq[j]) + 1e-12f);
}

// out[i] = [h2 | agg2[cat]] * inv_norm  — coalesced: warp = one row,
// thread = one float4 chunk (32 chunks of 4 floats per 128-col row).
__global__ __launch_bounds__(256) void k_scale(
    const void* __restrict__ cat, int aggIdx, float* __restrict__ out, int N)
{
    int gid = blockIdx.x * 256 + threadIdx.x;
    int row = gid >> 5, c4 = gid & 31;
    if (row >= N) return;
    const float* agg = g_agg + (size_t)aggIdx * NSEG * 64;
    float4 v;
    if (c4 < 16) {
        v = ((const float4*)&g_H[(size_t)row * 64])[c4];
    } else {
        int c = get_cat(cat, row, g_is64);
        v = ((const float4*)&agg[(size_t)c * 64])[c4 - 16];
    }
    float4 iv = ((const float4*)g_inv)[c4];
    ((float4*)&out[(size_t)row * 128])[c4] =
        make_float4(v.x * iv.x, v.y * iv.y, v.z * iv.z, v.w * iv.w);
}

// ---------------- launch ----------------
extern "C" void kernel_launch(void* const* d_in, const int* in_sizes, int n_in,
                              void* d_out, int out_size)
{
    const float* x  = (const float*)d_in[0];
    const void*  cat = d_in[1];
    int wb = (in_sizes[2] == 1) ? 3 : 2;
    const float* W0 = (const float*)d_in[wb + 0];
    const float* b0 = (const float*)d_in[wb + 1];
    const float* g0 = (const float*)d_in[wb + 2];
    const float* e0 = (const float*)d_in[wb + 3];
    const float* W1 = (const float*)d_in[wb + 4];
    const float* b1 = (const float*)d_in[wb + 5];
    const float* g1 = (const float*)d_in[wb + 6];
    const float* e1 = (const float*)d_in[wb + 7];
    const float* W2 = (const float*)d_in[wb + 8];
    const float* b2 = (const float*)d_in[wb + 9];
    const float* g2 = (const float*)d_in[wb + 10];
    const float* e2 = (const float*)d_in[wb + 11];

    int N = in_sizes[0] / 8;
    float* out = (float*)d_out;

    cudaFuncSetAttribute(k_layer0, cudaFuncAttributeMaxDynamicSharedMemorySize, L0_SMEM);
    cudaFuncSetAttribute(k_aggmm, cudaFuncAttributeMaxDynamicSharedMemorySize, AMM_SMEM);
    cudaFuncSetAttribute(k_layer<false>, cudaFuncAttributeMaxDynamicSharedMemorySize, SMEM_BYTES);
    cudaFuncSetAttribute(k_layer<true>,  cudaFuncAttributeMaxDynamicSharedMemorySize, SMEM_BYTES);

    int nblk = (N + 127) / 128;
    int nblk_s = (NSEG + 127) / 128;

    k_init<<<8192, 256>>>((const unsigned int*)cat);                 // launch 1
    k_layer0<<<nblk, 256, L0_SMEM>>>(x, cat, W0, b0, g0, e0, N);     // launch 2

    // layer 1: G = agg0 @ W1_bot ; then rows
    k_aggmm<<<nblk_s, 256, AMM_SMEM>>>(0, W1 + 64 * 64);             // launch 3
    k_layer<false><<<nblk, 256, SMEM_BYTES>>>(cat, 1, W1, b1, g1, e1, N);  // launch 4 <- ncu

    // layer 2
    k_aggmm<<<nblk_s, 256, AMM_SMEM>>>(1, W2 + 64 * 64);
    k_layer<true ><<<nblk, 256, SMEM_BYTES>>>(cat, 2, W2, b2, g2, e2, N);

    k_aggsq<<<512, 256>>>(2);
    k_inv<<<1, 128>>>();
    int sc_blocks = (int)(((long long)N * 32 + 255) / 256);
    k_scale<<<sc_blocks, 256>>>(cat, 2, out, N);
}

// round 11
// speedup vs baseline: 1.0457x; 1.0457x over previous
#include <cuda_runtime.h>
#include <cstdint>

// ---------------- static scratch (allocation-free rule) ----------------
#define NSEG 100000
#define NROWS_MAX 2000000

__device__ __align__(16) float g_H[(size_t)NROWS_MAX * 64];      // 512 MB
__device__ __align__(16) float g_agg[3u * NSEG * 64];            // 76.8 MB (L2-hot)
__device__ __align__(16) float g_G[(size_t)NSEG * 64];           // 25.6 MB (L2-hot)
__device__ int   g_cnt[NSEG];
__device__ float g_colsq[128];
__device__ float g_inv[128];
__device__ int   g_is64;

// ---------------- f32x2 packed-math helpers (sm_103a) ----------------
__device__ __forceinline__ unsigned long long pack2(float a, float b) {
    unsigned long long r;
    asm("mov.b64 %0, {%1, %2};" : "=l"(r) : "f"(a), "f"(b));
    return r;
}
__device__ __forceinline__ unsigned long long ffma2(unsigned long long a,
                                                    unsigned long long b,
                                                    unsigned long long c) {
    unsigned long long d;
    asm("fma.rn.f32x2 %0, %1, %2, %3;" : "=l"(d) : "l"(a), "l"(b), "l"(c));
    return d;
}
__device__ __forceinline__ void unpack2(unsigned long long v, float& a, float& b) {
    asm("mov.b64 {%0, %1}, %2;" : "=f"(a), "=f"(b) : "l"(v));
}

__device__ __forceinline__ int get_cat(const void* cat, int i, int is64) {
    if (is64) return (int)((const long long*)cat)[i];
    return ((const int*)cat)[i];
}

// filtered float atomicMax for non-negative floats (uint monotone)
__device__ __forceinline__ void agg_max(float* p, float h, float cur) {
    if (h > cur) atomicMax((unsigned int*)p, __float_as_uint(h));
}

// ---------------- kernels ----------------

// init + dtype detect fused (keeps k_layer<false> at launch index 4 for ncu)
__global__ void k_init(const unsigned int* cat) {
    int i = blockIdx.x * blockDim.x + threadIdx.x;
    if (blockIdx.x == 0 && threadIdx.x == 0) {
        int is64 = 1;
        for (int t = 0; t < 64; t++)
            if (cat[2 * t + 1] != 0u) { is64 = 0; break; }
        g_is64 = is64;
    }
    int stride = gridDim.x * blockDim.x;
    float4 z = make_float4(0.f, 0.f, 0.f, 0.f);
    float4* a4 = (float4*)g_agg;
    const int T4 = 3 * NSEG * 64 / 4;
    for (int j = i; j < T4; j += stride) a4[j] = z;
    for (int j = i; j < NSEG; j += stride) g_cnt[j] = 0;
    if (i < 128) g_colsq[i] = 0.f;
}

// ---------------- Layer 0 (tiled, low-reg, 4 CTAs/SM) ----------------
#define L0_XS_BYTES (128 * 8 * 4)        // 4096
#define L0_WS_BYTES (8 * 64 * 4)         // 2048
#define L0_CATS_OFF (L0_XS_BYTES + L0_WS_BYTES)
#define L0_SMEM     (L0_CATS_OFF + 512)

__global__ __launch_bounds__(256, 4) void k_layer0(
    const float* __restrict__ x, const void* __restrict__ cat,
    const float* __restrict__ W, const float* __restrict__ bia,
    const float* __restrict__ gam, const float* __restrict__ bet, int N)
{
    extern __shared__ char smem[];
    float* Xs = (float*)smem;                                   // [128][8]
    const ulonglong2* Wsp = (const ulonglong2*)(smem + L0_XS_BYTES); // [8][16]
    int* cats = (int*)(smem + L0_CATS_OFF);

    int tid = threadIdx.x;
    int base = blockIdx.x * 128;
    int is64 = g_is64;

    if (tid < 128) {
        int r = base + tid;
        int c = (r < N) ? get_cat(cat, r, is64) : 0;
        cats[tid] = c;
        if (r < N) atomicAdd(&g_cnt[c], 1);
    }
    if (tid < 128) {
        ((float4*)(smem + L0_XS_BYTES))[tid] = ((const float4*)W)[tid];
    }
    {
        int r = tid >> 1, c4 = tid & 1;
        int rg = base + r;
        float4 v = make_float4(0.f, 0.f, 0.f, 0.f);
        if (rg < N) v = ((const float4*)x)[(size_t)rg * 2 + c4];
        ((float4*)Xs)[tid] = v;
    }
    __syncthreads();

    int tx = tid & 15, tyg = tid >> 4;
    int r0 = tyg * 8;

    unsigned long long acc[8][2];
#pragma unroll
    for (int i = 0; i < 8; i++) { acc[i][0] = 0ull; acc[i][1] = 0ull; }

#pragma unroll
    for (int k4 = 0; k4 < 2; k4++) {
        ulonglong2 w0 = Wsp[(k4 * 4 + 0) * 16 + tx];
        ulonglong2 w1 = Wsp[(k4 * 4 + 1) * 16 + tx];
        ulonglong2 w2 = Wsp[(k4 * 4 + 2) * 16 + tx];
        ulonglong2 w3 = Wsp[(k4 * 4 + 3) * 16 + tx];
#pragma unroll
        for (int i = 0; i < 8; i++) {
            float4 xv = ((const float4*)(Xs + (r0 + i) * 8))[k4];
            unsigned long long d;
            d = pack2(xv.x, xv.x);
            acc[i][0] = ffma2(d, w0.x, acc[i][0]); acc[i][1] = ffma2(d, w0.y, acc[i][1]);
            d = pack2(xv.y, xv.y);
            acc[i][0] = ffma2(d, w1.x, acc[i][0]); acc[i][1] = ffma2(d, w1.y, acc[i][1]);
            d = pack2(xv.z, xv.z);
            acc[i][0] = ffma2(d, w2.x, acc[i][0]); acc[i][1] = ffma2(d, w2.y, acc[i][1]);
            d = pack2(xv.w, xv.w);
            acc[i][0] = ffma2(d, w3.x, acc[i][0]); acc[i][1] = ffma2(d, w3.y, acc[i][1]);
        }
    }

    int c0 = tx * 4;
    float4 bv  = *(const float4*)&bia[c0];
    float4 gv  = *(const float4*)&gam[c0];
    float4 bev = *(const float4*)&bet[c0];

    float* agg0 = g_agg;

#pragma unroll
    for (int i = 0; i < 8; i++) {
        int rg = base + r0 + i;
        int ci = cats[r0 + i];
        float4 cur = *(const float4*)(agg0 + (size_t)ci * 64 + c0);
        float a0, a1, a2, a3;
        unpack2(acc[i][0], a0, a1);
        unpack2(acc[i][1], a2, a3);
        a0 += bv.x; a1 += bv.y; a2 += bv.z; a3 += bv.w;
        float s1 = a0 + a1 + a2 + a3;
        float s2 = a0 * a0 + a1 * a1 + a2 * a2 + a3 * a3;
#pragma unroll
        for (int m = 1; m < 16; m <<= 1) {
            s1 += __shfl_xor_sync(0xffffffffu, s1, m);
            s2 += __shfl_xor_sync(0xffffffffu, s2, m);
        }
        float mean = s1 * (1.f / 64.f);
        float var  = s2 * (1.f / 64.f) - mean * mean;
        float rs   = rsqrtf(var + 1e-5f);
        float h0 = fmaxf(fmaf((a0 - mean) * rs, gv.x, bev.x), 0.f);
        float h1 = fmaxf(fmaf((a1 - mean) * rs, gv.y, bev.y), 0.f);
        float h2 = fmaxf(fmaf((a2 - mean) * rs, gv.z, bev.z), 0.f);
        float h3 = fmaxf(fmaf((a3 - mean) * rs, gv.w, bev.w), 0.f);
        if (rg < N) {
            ((float4*)&g_H[(size_t)rg * 64])[tx] = make_float4(h0, h1, h2, h3);
            float* ap = agg0 + (size_t)ci * 64 + c0;
            agg_max(ap + 0, h0, cur.x);
            agg_max(ap + 1, h1, cur.y);
            agg_max(ap + 2, h2, cur.z);
            agg_max(ap + 3, h3, cur.w);
        }
    }
}

// ---------------- G = agg @ W_bot  (per-segment precompute) ----------------
#define AMM_SMEM (128 * 64 * 4 + 64 * 64 * 4)   // 49152

__global__ __launch_bounds__(256, 3) void k_aggmm(int aggInIdx, const float* __restrict__ Wbot)
{
    extern __shared__ char smem[];
    float* As = (float*)smem;
    const ulonglong2* Wsp = (const ulonglong2*)(smem + 128 * 64 * 4);
    const float* agg = g_agg + (size_t)aggInIdx * NSEG * 64;

    int tid = threadIdx.x;
    int base = blockIdx.x * 128;

    {
        const float4* Wv = (const float4*)Wbot;
        float4* Wd = (float4*)(smem + 128 * 64 * 4);
#pragma unroll
        for (int t = 0; t < 4; t++) Wd[tid + t * 256] = Wv[tid + t * 256];
    }
    {
#pragma unroll
        for (int t = 0; t < 8; t++) {
            int idx = tid + t * 256;
            int r = idx >> 4, c4 = idx & 15;
            int rg = base + r;
            float4 v = make_float4(0.f, 0.f, 0.f, 0.f);
            if (rg < NSEG) v = ((const float4*)&agg[(size_t)rg * 64])[c4];
            ((float4*)&As[r * 64])[c4] = v;
        }
    }
    __syncthreads();

    int tx = tid & 15, tyg = tid >> 4;
    int r0 = tyg * 8;

    unsigned long long acc[8][2];
#pragma unroll
    for (int i = 0; i < 8; i++) { acc[i][0] = 0ull; acc[i][1] = 0ull; }

#pragma unroll 4
    for (int k4 = 0; k4 < 16; k4++) {
        ulonglong2 w0 = Wsp[(k4 * 4 + 0) * 16 + tx];
        ulonglong2 w1 = Wsp[(k4 * 4 + 1) * 16 + tx];
        ulonglong2 w2 = Wsp[(k4 * 4 + 2) * 16 + tx];
        ulonglong2 w3 = Wsp[(k4 * 4 + 3) * 16 + tx];
#pragma unroll
        for (int i = 0; i < 8; i++) {
            float4 xv = ((const float4*)(As + (r0 + i) * 64))[k4];
            unsigned long long d;
            d = pack2(xv.x, xv.x);
            acc[i][0] = ffma2(d, w0.x, acc[i][0]); acc[i][1] = ffma2(d, w0.y, acc[i][1]);
            d = pack2(xv.y, xv.y);
            acc[i][0] = ffma2(d, w1.x, acc[i][0]); acc[i][1] = ffma2(d, w1.y, acc[i][1]);
            d = pack2(xv.z, xv.z);
            acc[i][0] = ffma2(d, w2.x, acc[i][0]); acc[i][1] = ffma2(d, w2.y, acc[i][1]);
            d = pack2(xv.w, xv.w);
            acc[i][0] = ffma2(d, w3.x, acc[i][0]); acc[i][1] = ffma2(d, w3.y, acc[i][1]);
        }
    }

    int c0 = tx * 4;
#pragma unroll
    for (int i = 0; i < 8; i++) {
        int rg = base + r0 + i;
        if (rg < NSEG) {
            float a0, a1, a2, a3;
            unpack2(acc[i][0], a0, a1);
            unpack2(acc[i][1], a2, a3);
            *(float4*)&g_G[(size_t)rg * 64 + c0] = make_float4(a0, a1, a2, a3);
        }
    }
}

// ---------------- Layers 1/2 (row-in-one-warp tile, occ 3, epilogue G) -----
// 256 threads; thread tile 4 rows x 8 cols.
//   txg = l & 7           (8 col-groups of 8; whole row within one warp)
//   tyg = w*4 | (l>>3)    (32 row-groups of 4)
// LN reduction = 3 shfl links over the 8 lanes sharing a row.
// Xs chunk-swizzled: logical chunk c4 of row r stored at c4 ^ ((r>>2)&7).
// G[cat] gathered batched at epilogue start (no mainloop register tax).
#define XS_BYTES  (128 * 64 * 4)                 // 32768
#define WS_BYTES  (64 * 64 * 4)                  // 16384
#define CATS_OFF  (XS_BYTES + WS_BYTES)          // 49152
#define SCSQ_OFF  (CATS_OFF + 512)               // 49664
#define SMEM_BYTES (SCSQ_OFF + 256)              // 49920

template <bool COLSQ>
__global__ __launch_bounds__(256, 3) void k_layer(
    const void* __restrict__ cat, int aggOutIdx,
    const float* __restrict__ Wtop, const float* __restrict__ bia,
    const float* __restrict__ gam, const float* __restrict__ bet, int N)
{
    extern __shared__ char smem[];
    float* Xs = (float*)smem;                                  // [128][64] swizzled
    const float* Ws = (const float*)(smem + XS_BYTES);         // [64][64]
    int* cats = (int*)(smem + CATS_OFF);
    float* scolsq = (float*)(smem + SCSQ_OFF);

    float* aggOut = g_agg + (size_t)aggOutIdx * NSEG * 64;

    int tid = threadIdx.x;
    int base = blockIdx.x * 128;
    int is64 = g_is64;
    int w_ = tid >> 5, l = tid & 31;

    if (tid < 128) {
        int r = base + tid;
        cats[tid] = (r < N) ? get_cat(cat, r, is64) : 0;
    }
    {   // W_top: 1024 float4 (plain layout)
        const float4* Wv = (const float4*)Wtop;
        float4* Wd = (float4*)(smem + XS_BYTES);
#pragma unroll
        for (int t = 0; t < 4; t++) Wd[tid + t * 256] = Wv[tid + t * 256];
    }
    {   // Xs = H tile: 2048 float4, chunk-swizzled per row
#pragma unroll
        for (int t = 0; t < 8; t++) {
            int idx = tid + t * 256;
            int r = idx >> 4, c4 = idx & 15;
            int rg = base + r;
            float4 v = make_float4(0.f, 0.f, 0.f, 0.f);
            if (rg < N) v = ((const float4*)&g_H[(size_t)rg * 64])[c4];
            ((float4*)Xs)[r * 16 + (c4 ^ ((r >> 2) & 7))] = v;
        }
    }
    __syncthreads();

    int txg = l & 7;                 // 0..7
    int tyg = (w_ << 2) | (l >> 3);  // 0..31
    int r0 = tyg * 4;
    int c0 = txg * 8;

    // acc init = bias only (f32x2-packed); G added in epilogue
    float4 biaA = *(const float4*)&bia[c0];
    float4 biaB = *(const float4*)&bia[c0 + 4];
    unsigned long long acc[4][4];
#pragma unroll
    for (int i = 0; i < 4; i++) {
        acc[i][0] = pack2(biaA.x, biaA.y);
        acc[i][1] = pack2(biaA.z, biaA.w);
        acc[i][2] = pack2(biaB.x, biaB.y);
        acc[i][3] = pack2(biaB.z, biaB.w);
    }

#define K4BODY(J, X0, X1, X2, X3) { \
    const float* wrow = Ws + (k4 * 4 + (J)) * 64 + c0; \
    ulonglong2 wA = *(const ulonglong2*)wrow; \
    ulonglong2 wB = *(const ulonglong2*)(wrow + 4); \
    unsigned long long d; \
    d = pack2(X0, X0); \
    acc[0][0] = ffma2(d, wA.x, acc[0][0]); acc[0][1] = ffma2(d, wA.y, acc[0][1]); \
    acc[0][2] = ffma2(d, wB.x, acc[0][2]); acc[0][3] = ffma2(d, wB.y, acc[0][3]); \
    d = pack2(X1, X1); \
    acc[1][0] = ffma2(d, wA.x, acc[1][0]); acc[1][1] = ffma2(d, wA.y, acc[1][1]); \
    acc[1][2] = ffma2(d, wB.x, acc[1][2]); acc[1][3] = ffma2(d, wB.y, acc[1][3]); \
    d = pack2(X2, X2); \
    acc[2][0] = ffma2(d, wA.x, acc[2][0]); acc[2][1] = ffma2(d, wA.y, acc[2][1]); \
    acc[2][2] = ffma2(d, wB.x, acc[2][2]); acc[2][3] = ffma2(d, wB.y, acc[2][3]); \
    d = pack2(X3, X3); \
    acc[3][0] = ffma2(d, wA.x, acc[3][0]); acc[3][1] = ffma2(d, wA.y, acc[3][1]); \
    acc[3][2] = ffma2(d, wB.x, acc[3][2]); acc[3][3] = ffma2(d, wB.y, acc[3][3]); \
}

#pragma unroll 4
    for (int k4 = 0; k4 < 16; k4++) {
        int chunk = k4 ^ (tyg & 7);
        float4 xv0 = ((const float4*)Xs)[(r0 + 0) * 16 + chunk];
        float4 xv1 = ((const float4*)Xs)[(r0 + 1) * 16 + chunk];
        float4 xv2 = ((const float4*)Xs)[(r0 + 2) * 16 + chunk];
        float4 xv3 = ((const float4*)Xs)[(r0 + 3) * 16 + chunk];
        K4BODY(0, xv0.x, xv1.x, xv2.x, xv3.x)
        K4BODY(1, xv0.y, xv1.y, xv2.y, xv3.y)
        K4BODY(2, xv0.z, xv1.z, xv2.z, xv3.z)
        K4BODY(3, xv0.w, xv1.w, xv2.w, xv3.w)
    }
#undef K4BODY

    // ---- epilogue: batched G gather (MLP), then stream rows ----
    float4 gA[4], gB[4];
#pragma unroll
    for (int i = 0; i < 4; i++) {
        const float* gp = &g_G[(size_t)cats[r0 + i] * 64 + c0];
        gA[i] = *(const float4*)gp;
        gB[i] = *(const float4*)(gp + 4);
    }

    float4 gvA = *(const float4*)&gam[c0];
    float4 gvB = *(const float4*)&gam[c0 + 4];
    float4 beA = *(const float4*)&bet[c0];
    float4 beB = *(const float4*)&bet[c0 + 4];
    float csq[8];
#pragma unroll
    for (int j = 0; j < 8; j++) csq[j] = 0.f;

#pragma unroll
    for (int i = 0; i < 4; i++) {
        float a0, a1, a2, a3, a4, a5, a6, a7;
        unpack2(acc[i][0], a0, a1);
        unpack2(acc[i][1], a2, a3);
        unpack2(acc[i][2], a4, a5);
        unpack2(acc[i][3], a6, a7);
        a0 += gA[i].x; a1 += gA[i].y; a2 += gA[i].z; a3 += gA[i].w;
        a4 += gB[i].x; a5 += gB[i].y; a6 += gB[i].z; a7 += gB[i].w;
        float s1 = ((a0 + a1) + (a2 + a3)) + ((a4 + a5) + (a6 + a7));
        float s2 = ((a0 * a0 + a1 * a1) + (a2 * a2 + a3 * a3))
                 + ((a4 * a4 + a5 * a5) + (a6 * a6 + a7 * a7));
        s1 += __shfl_xor_sync(0xffffffffu, s1, 1);
        s2 += __shfl_xor_sync(0xffffffffu, s2, 1);
        s1 += __shfl_xor_sync(0xffffffffu, s1, 2);
        s2 += __shfl_xor_sync(0xffffffffu, s2, 2);
        s1 += __shfl_xor_sync(0xffffffffu, s1, 4);
        s2 += __shfl_xor_sync(0xffffffffu, s2, 4);
        float mean = s1 * (1.f / 64.f);
        float var  = s2 * (1.f / 64.f) - mean * mean;
        float rs   = rsqrtf(var + 1e-5f);
        float h0 = fmaxf(fmaf((a0 - mean) * rs, gvA.x, beA.x), 0.f);
        float h1 = fmaxf(fmaf((a1 - mean) * rs, gvA.y, beA.y), 0.f);
        float h2 = fmaxf(fmaf((a2 - mean) * rs, gvA.z, beA.z), 0.f);
        float h3 = fmaxf(fmaf((a3 - mean) * rs, gvA.w, beA.w), 0.f);
        float h4 = fmaxf(fmaf((a4 - mean) * rs, gvB.x, beB.x), 0.f);
        float h5 = fmaxf(fmaf((a5 - mean) * rs, gvB.y, beB.y), 0.f);
        float h6 = fmaxf(fmaf((a6 - mean) * rs, gvB.z, beB.z), 0.f);
        float h7 = fmaxf(fmaf((a7 - mean) * rs, gvB.w, beB.w), 0.f);
        int rg = base + r0 + i;
        if (rg < N) {
            int ci = cats[r0 + i];
            float4* hp = (float4*)&g_H[(size_t)rg * 64 + c0];
            hp[0] = make_float4(h0, h1, h2, h3);
            hp[1] = make_float4(h4, h5, h6, h7);
            float* ap = aggOut + (size_t)ci * 64 + c0;
            float4 curA = *(const float4*)ap;
            float4 curB = *(const float4*)(ap + 4);
            agg_max(ap + 0, h0, curA.x);
            agg_max(ap + 1, h1, curA.y);
            agg_max(ap + 2, h2, curA.z);
            agg_max(ap + 3, h3, curA.w);
            agg_max(ap + 4, h4, curB.x);
            agg_max(ap + 5, h5, curB.y);
            agg_max(ap + 6, h6, curB.z);
            agg_max(ap + 7, h7, curB.w);
            if (COLSQ) {
                csq[0] = fmaf(h0, h0, csq[0]); csq[1] = fmaf(h1, h1, csq[1]);
                csq[2] = fmaf(h2, h2, csq[2]); csq[3] = fmaf(h3, h3, csq[3]);
                csq[4] = fmaf(h4, h4, csq[4]); csq[5] = fmaf(h5, h5, csq[5]);
                csq[6] = fmaf(h6, h6, csq[6]); csq[7] = fmaf(h7, h7, csq[7]);
            }
        }
    }
    if (COLSQ) {
        if (tid < 64) scolsq[tid] = 0.f;
        __syncthreads();
#pragma unroll
        for (int j = 0; j < 8; j++) atomicAdd(&scolsq[c0 + j], csq[j]);
        __syncthreads();
        if (tid < 64) atomicAdd(&g_colsq[tid], scolsq[tid]);
    }
}

// colsq for agg half: sum_s count[s] * agg2[s,j]^2  (L2-hot)
__global__ void k_aggsq(int aggIdx) {
    const float* agg = g_agg + (size_t)aggIdx * NSEG * 64;
    int j = threadIdx.x & 63;
    int sb_ = threadIdx.x >> 6;
    float acc = 0.f;
    for (int s = blockIdx.x * 4 + sb_; s < NSEG; s += gridDim.x * 4) {
        float cnt = (float)g_cnt[s];
        if (cnt > 0.f) {
            float v = agg[(size_t)s * 64 + j];
            acc = fmaf(cnt, v * v, acc);
        }
    }
    __shared__ float red[64];
    if (threadIdx.x < 64) red[threadIdx.x] = 0.f;
    __syncthreads();
    atomicAdd(&red[j], acc);
    __syncthreads();
    if (threadIdx.x < 64) atomicAdd(&g_colsq[64 + threadIdx.x], red[threadIdx.x]);
}

__global__ void k_inv() {
    int j = threadIdx.x;
    if (j < 128) g_inv[j] = 1.f / (sqrtf(g_colsq[j]) + 1e-12f);
}

// out[i] = [h2 | agg2[cat]] * inv_norm  — coalesced: warp = one row,
// thread = one float4 chunk (32 chunks of 4 floats per 128-col row).
__global__ __launch_bounds__(256) void k_scale(
    const void* __restrict__ cat, int aggIdx, float* __restrict__ out, int N)
{
    int gid = blockIdx.x * 256 + threadIdx.x;
    int row = gid >> 5, c4 = gid & 31;
    if (row >= N) return;
    const float* agg = g_agg + (size_t)aggIdx * NSEG * 64;
    float4 v;
    if (c4 < 16) {
        v = ((const float4*)&g_H[(size_t)row * 64])[c4];
    } else {
        int c = get_cat(cat, row, g_is64);
        v = ((const float4*)&agg[(size_t)c * 64])[c4 - 16];
    }
    float4 iv = ((const float4*)g_inv)[c4];
    ((float4*)&out[(size_t)row * 128])[c4] =
        make_float4(v.x * iv.x, v.y * iv.y, v.z * iv.z, v.w * iv.w);
}

// ---------------- launch ----------------
extern "C" void kernel_launch(void* const* d_in, const int* in_sizes, int n_in,
                              void* d_out, int out_size)
{
    const float* x  = (const float*)d_in[0];
    const void*  cat = d_in[1];
    int wb = (in_sizes[2] == 1) ? 3 : 2;
    const float* W0 = (const float*)d_in[wb + 0];
    const float* b0 = (const float*)d_in[wb + 1];
    const float* g0 = (const float*)d_in[wb + 2];
    const float* e0 = (const float*)d_in[wb + 3];
    const float* W1 = (const float*)d_in[wb + 4];
    const float* b1 = (const float*)d_in[wb + 5];
    const float* g1 = (const float*)d_in[wb + 6];
    const float* e1 = (const float*)d_in[wb + 7];
    const float* W2 = (const float*)d_in[wb + 8];
    const float* b2 = (const float*)d_in[wb + 9];
    const float* g2 = (const float*)d_in[wb + 10];
    const float* e2 = (const float*)d_in[wb + 11];

    int N = in_sizes[0] / 8;
    float* out = (float*)d_out;

    cudaFuncSetAttribute(k_layer0, cudaFuncAttributeMaxDynamicSharedMemorySize, L0_SMEM);
    cudaFuncSetAttribute(k_aggmm, cudaFuncAttributeMaxDynamicSharedMemorySize, AMM_SMEM);
    cudaFuncSetAttribute(k_layer<false>, cudaFuncAttributeMaxDynamicSharedMemorySize, SMEM_BYTES);
    cudaFuncSetAttribute(k_layer<true>,  cudaFuncAttributeMaxDynamicSharedMemorySize, SMEM_BYTES);

    int nblk = (N + 127) / 128;
    int nblk_s = (NSEG + 127) / 128;

    k_init<<<8192, 256>>>((const unsigned int*)cat);                 // launch 1
    k_layer0<<<nblk, 256, L0_SMEM>>>(x, cat, W0, b0, g0, e0, N);     // launch 2

    // layer 1: G = agg0 @ W1_bot ; then rows
    k_aggmm<<<nblk_s, 256, AMM_SMEM>>>(0, W1 + 64 * 64);             // launch 3
    k_layer<false><<<nblk, 256, SMEM_BYTES>>>(cat, 1, W1, b1, g1, e1, N);  // launch 4 <- ncu

    // layer 2
    k_aggmm<<<nblk_s, 256, AMM_SMEM>>>(1, W2 + 64 * 64);
    k_layer<true ><<<nblk, 256, SMEM_BYTES>>>(cat, 2, W2, b2, g2, e2, N);

    k_aggsq<<<512, 256>>>(2);
    k_inv<<<1, 128>>>();
    int sc_blocks = (int)(((long long)N * 32 + 255) / 256);
    k_scale<<<sc_blocks, 256>>>(cat, 2, out, N);
}

// round 12
// speedup vs baseline: 1.2764x; 1.2206x over previous
#include <cuda_runtime.h>
#include <cstdint>

// ---------------- static scratch (allocation-free rule) ----------------
#define NSEG 100000
#define NROWS_MAX 2000000

__device__ __align__(16) float g_H[(size_t)NROWS_MAX * 64];      // 512 MB
__device__ __align__(16) float g_agg[3u * NSEG * 64];            // 76.8 MB (L2-hot)
__device__ __align__(16) float g_G[(size_t)NSEG * 64];           // 25.6 MB (L2-hot)
__device__ int   g_cnt[NSEG];
__device__ float g_colsq[128];
__device__ float g_inv[128];
__device__ int   g_is64;

// ---------------- f32x2 packed-math helpers (sm_103a) ----------------
__device__ __forceinline__ unsigned long long pack2(float a, float b) {
    unsigned long long r;
    asm("mov.b64 %0, {%1, %2};" : "=l"(r) : "f"(a), "f"(b));
    return r;
}
__device__ __forceinline__ unsigned long long ffma2(unsigned long long a,
                                                    unsigned long long b,
                                                    unsigned long long c) {
    unsigned long long d;
    asm("fma.rn.f32x2 %0, %1, %2, %3;" : "=l"(d) : "l"(a), "l"(b), "l"(c));
    return d;
}
__device__ __forceinline__ void unpack2(unsigned long long v, float& a, float& b) {
    asm("mov.b64 {%0, %1}, %2;" : "=f"(a), "=f"(b) : "l"(v));
}

__device__ __forceinline__ int get_cat(const void* cat, int i, int is64) {
    if (is64) return (int)((const long long*)cat)[i];
    return ((const int*)cat)[i];
}

// filtered float atomicMax for non-negative floats (uint monotone)
__device__ __forceinline__ void agg_max(float* p, float h, float cur) {
    if (h > cur) atomicMax((unsigned int*)p, __float_as_uint(h));
}

// ---------------- kernels ----------------

// init + dtype detect fused (keeps k_layer<false> at launch index 4 for ncu)
__global__ void k_init(const unsigned int* cat) {
    int i = blockIdx.x * blockDim.x + threadIdx.x;
    if (blockIdx.x == 0 && threadIdx.x == 0) {
        int is64 = 1;
        for (int t = 0; t < 64; t++)
            if (cat[2 * t + 1] != 0u) { is64 = 0; break; }
        g_is64 = is64;
    }
    int stride = gridDim.x * blockDim.x;
    float4 z = make_float4(0.f, 0.f, 0.f, 0.f);
    float4* a4 = (float4*)g_agg;
    const int T4 = 3 * NSEG * 64 / 4;
    for (int j = i; j < T4; j += stride) a4[j] = z;
    for (int j = i; j < NSEG; j += stride) g_cnt[j] = 0;
    if (i < 128) g_colsq[i] = 0.f;
}

// ---------------- Layer 0 (tiled, low-reg, 4 CTAs/SM) ----------------
#define L0_XS_BYTES (128 * 8 * 4)        // 4096
#define L0_WS_BYTES (8 * 64 * 4)         // 2048
#define L0_CATS_OFF (L0_XS_BYTES + L0_WS_BYTES)
#define L0_SMEM     (L0_CATS_OFF + 512)

__global__ __launch_bounds__(256, 4) void k_layer0(
    const float* __restrict__ x, const void* __restrict__ cat,
    const float* __restrict__ W, const float* __restrict__ bia,
    const float* __restrict__ gam, const float* __restrict__ bet, int N)
{
    extern __shared__ char smem[];
    float* Xs = (float*)smem;                                   // [128][8]
    const ulonglong2* Wsp = (const ulonglong2*)(smem + L0_XS_BYTES); // [8][16]
    int* cats = (int*)(smem + L0_CATS_OFF);

    int tid = threadIdx.x;
    int base = blockIdx.x * 128;
    int is64 = g_is64;

    if (tid < 128) {
        int r = base + tid;
        int c = (r < N) ? get_cat(cat, r, is64) : 0;
        cats[tid] = c;
        if (r < N) atomicAdd(&g_cnt[c], 1);
    }
    if (tid < 128) {
        ((float4*)(smem + L0_XS_BYTES))[tid] = ((const float4*)W)[tid];
    }
    {
        int r = tid >> 1, c4 = tid & 1;
        int rg = base + r;
        float4 v = make_float4(0.f, 0.f, 0.f, 0.f);
        if (rg < N) v = ((const float4*)x)[(size_t)rg * 2 + c4];
        ((float4*)Xs)[tid] = v;
    }
    __syncthreads();

    int tx = tid & 15, tyg = tid >> 4;
    int r0 = tyg * 8;

    unsigned long long acc[8][2];
#pragma unroll
    for (int i = 0; i < 8; i++) { acc[i][0] = 0ull; acc[i][1] = 0ull; }

#pragma unroll
    for (int k4 = 0; k4 < 2; k4++) {
        ulonglong2 w0 = Wsp[(k4 * 4 + 0) * 16 + tx];
        ulonglong2 w1 = Wsp[(k4 * 4 + 1) * 16 + tx];
        ulonglong2 w2 = Wsp[(k4 * 4 + 2) * 16 + tx];
        ulonglong2 w3 = Wsp[(k4 * 4 + 3) * 16 + tx];
#pragma unroll
        for (int i = 0; i < 8; i++) {
            float4 xv = ((const float4*)(Xs + (r0 + i) * 8))[k4];
            unsigned long long d;
            d = pack2(xv.x, xv.x);
            acc[i][0] = ffma2(d, w0.x, acc[i][0]); acc[i][1] = ffma2(d, w0.y, acc[i][1]);
            d = pack2(xv.y, xv.y);
            acc[i][0] = ffma2(d, w1.x, acc[i][0]); acc[i][1] = ffma2(d, w1.y, acc[i][1]);
            d = pack2(xv.z, xv.z);
            acc[i][0] = ffma2(d, w2.x, acc[i][0]); acc[i][1] = ffma2(d, w2.y, acc[i][1]);
            d = pack2(xv.w, xv.w);
            acc[i][0] = ffma2(d, w3.x, acc[i][0]); acc[i][1] = ffma2(d, w3.y, acc[i][1]);
        }
    }

    int c0 = tx * 4;
    float4 bv  = *(const float4*)&bia[c0];
    float4 gv  = *(const float4*)&gam[c0];
    float4 bev = *(const float4*)&bet[c0];

    float* agg0 = g_agg;

#pragma unroll
    for (int i = 0; i < 8; i++) {
        int rg = base + r0 + i;
        int ci = cats[r0 + i];
        float4 cur = *(const float4*)(agg0 + (size_t)ci * 64 + c0);
        float a0, a1, a2, a3;
        unpack2(acc[i][0], a0, a1);
        unpack2(acc[i][1], a2, a3);
        a0 += bv.x; a1 += bv.y; a2 += bv.z; a3 += bv.w;
        float s1 = a0 + a1 + a2 + a3;
        float s2 = a0 * a0 + a1 * a1 + a2 * a2 + a3 * a3;
#pragma unroll
        for (int m = 1; m < 16; m <<= 1) {
            s1 += __shfl_xor_sync(0xffffffffu, s1, m);
            s2 += __shfl_xor_sync(0xffffffffu, s2, m);
        }
        float mean = s1 * (1.f / 64.f);
        float var  = s2 * (1.f / 64.f) - mean * mean;
        float rs   = rsqrtf(var + 1e-5f);
        float h0 = fmaxf(fmaf((a0 - mean) * rs, gv.x, bev.x), 0.f);
        float h1 = fmaxf(fmaf((a1 - mean) * rs, gv.y, bev.y), 0.f);
        float h2 = fmaxf(fmaf((a2 - mean) * rs, gv.z, bev.z), 0.f);
        float h3 = fmaxf(fmaf((a3 - mean) * rs, gv.w, bev.w), 0.f);
        if (rg < N) {
            ((float4*)&g_H[(size_t)rg * 64])[tx] = make_float4(h0, h1, h2, h3);
            float* ap = agg0 + (size_t)ci * 64 + c0;
            agg_max(ap + 0, h0, cur.x);
            agg_max(ap + 1, h1, cur.y);
            agg_max(ap + 2, h2, cur.z);
            agg_max(ap + 3, h3, cur.w);
        }
    }
}

// ---------------- G = agg @ W_bot  (per-segment precompute) ----------------
#define AMM_SMEM (128 * 64 * 4 + 64 * 64 * 4)   // 49152

__global__ __launch_bounds__(256, 3) void k_aggmm(int aggInIdx, const float* __restrict__ Wbot)
{
    extern __shared__ char smem[];
    float* As = (float*)smem;
    const ulonglong2* Wsp = (const ulonglong2*)(smem + 128 * 64 * 4);
    const float* agg = g_agg + (size_t)aggInIdx * NSEG * 64;

    int tid = threadIdx.x;
    int base = blockIdx.x * 128;

    {
        const float4* Wv = (const float4*)Wbot;
        float4* Wd = (float4*)(smem + 128 * 64 * 4);
#pragma unroll
        for (int t = 0; t < 4; t++) Wd[tid + t * 256] = Wv[tid + t * 256];
    }
    {
#pragma unroll
        for (int t = 0; t < 8; t++) {
            int idx = tid + t * 256;
            int r = idx >> 4, c4 = idx & 15;
            int rg = base + r;
            float4 v = make_float4(0.f, 0.f, 0.f, 0.f);
            if (rg < NSEG) v = ((const float4*)&agg[(size_t)rg * 64])[c4];
            ((float4*)&As[r * 64])[c4] = v;
        }
    }
    __syncthreads();

    int tx = tid & 15, tyg = tid >> 4;
    int r0 = tyg * 8;

    unsigned long long acc[8][2];
#pragma unroll
    for (int i = 0; i < 8; i++) { acc[i][0] = 0ull; acc[i][1] = 0ull; }

#pragma unroll 4
    for (int k4 = 0; k4 < 16; k4++) {
        ulonglong2 w0 = Wsp[(k4 * 4 + 0) * 16 + tx];
        ulonglong2 w1 = Wsp[(k4 * 4 + 1) * 16 + tx];
        ulonglong2 w2 = Wsp[(k4 * 4 + 2) * 16 + tx];
        ulonglong2 w3 = Wsp[(k4 * 4 + 3) * 16 + tx];
#pragma unroll
        for (int i = 0; i < 8; i++) {
            float4 xv = ((const float4*)(As + (r0 + i) * 64))[k4];
            unsigned long long d;
            d = pack2(xv.x, xv.x);
            acc[i][0] = ffma2(d, w0.x, acc[i][0]); acc[i][1] = ffma2(d, w0.y, acc[i][1]);
            d = pack2(xv.y, xv.y);
            acc[i][0] = ffma2(d, w1.x, acc[i][0]); acc[i][1] = ffma2(d, w1.y, acc[i][1]);
            d = pack2(xv.z, xv.z);
            acc[i][0] = ffma2(d, w2.x, acc[i][0]); acc[i][1] = ffma2(d, w2.y, acc[i][1]);
            d = pack2(xv.w, xv.w);
            acc[i][0] = ffma2(d, w3.x, acc[i][0]); acc[i][1] = ffma2(d, w3.y, acc[i][1]);
        }
    }

    int c0 = tx * 4;
#pragma unroll
    for (int i = 0; i < 8; i++) {
        int rg = base + r0 + i;
        if (rg < NSEG) {
            float a0, a1, a2, a3;
            unpack2(acc[i][0], a0, a1);
            unpack2(acc[i][1], a2, a3);
            *(float4*)&g_G[(size_t)rg * 64 + c0] = make_float4(a0, a1, a2, a3);
        }
    }
}

// ---------------- Layers 1/2 (round-7 balanced warp tile — best measured) ---
// 256 threads; thread tile 4 rows x 8 cols.
//   txg = (w&1)*4 | (l&3)   (8 col-groups of 8)
//   tyg = (w>>1)*8 | (l>>2) (32 row-groups of 4)
// Xs chunk-swizzled: logical chunk c4 of row r stored at c4 ^ ((r>>2)&7).
#define XS_BYTES  (128 * 64 * 4)                 // 32768
#define WS_BYTES  (64 * 64 * 4)                  // 16384
#define CATS_OFF  (XS_BYTES + WS_BYTES)          // 49152
#define SRED_OFF  (CATS_OFF + 512)               // 49664
#define SCSQ_OFF  (SRED_OFF + 128 * 16)          // 51712
#define SMEM_BYTES (SCSQ_OFF + 256)              // 51968

template <bool COLSQ>
__global__ __launch_bounds__(256, 3) void k_layer(
    const void* __restrict__ cat, int aggOutIdx,
    const float* __restrict__ Wtop, const float* __restrict__ bia,
    const float* __restrict__ gam, const float* __restrict__ bet, int N)
{
    extern __shared__ char smem[];
    float* Xs = (float*)smem;                                  // [128][64] swizzled
    const float* Ws = (const float*)(smem + XS_BYTES);         // [64][64]
    int* cats = (int*)(smem + CATS_OFF);
    float* sred = (float*)(smem + SRED_OFF);                   // [128][4]
    float* scolsq = (float*)(smem + SCSQ_OFF);

    float* aggOut = g_agg + (size_t)aggOutIdx * NSEG * 64;

    int tid = threadIdx.x;
    int base = blockIdx.x * 128;
    int is64 = g_is64;
    int w_ = tid >> 5, l = tid & 31;

    if (tid < 128) {
        int r = base + tid;
        cats[tid] = (r < N) ? get_cat(cat, r, is64) : 0;
    }
    {   // W_top: 1024 float4 (plain layout)
        const float4* Wv = (const float4*)Wtop;
        float4* Wd = (float4*)(smem + XS_BYTES);
#pragma unroll
        for (int t = 0; t < 4; t++) Wd[tid + t * 256] = Wv[tid + t * 256];
    }
    {   // Xs = H tile: 2048 float4, chunk-swizzled per row
#pragma unroll
        for (int t = 0; t < 8; t++) {
            int idx = tid + t * 256;
            int r = idx >> 4, c4 = idx & 15;
            int rg = base + r;
            float4 v = make_float4(0.f, 0.f, 0.f, 0.f);
            if (rg < N) v = ((const float4*)&g_H[(size_t)rg * 64])[c4];
            ((float4*)Xs)[r * 16 + (c4 ^ ((r >> 2) & 7))] = v;
        }
    }
    __syncthreads();

    int txg = ((w_ & 1) << 2) | (l & 3);     // 0..7
    int tyg = ((w_ >> 1) << 3) | (l >> 2);   // 0..31
    int r0 = tyg * 4;
    int c0 = txg * 8;

    unsigned long long acc[4][4];
#pragma unroll
    for (int i = 0; i < 4; i++)
#pragma unroll
        for (int c = 0; c < 4; c++) acc[i][c] = 0ull;

#define K4BODY(J, X0, X1, X2, X3) { \
    const float* wrow = Ws + (k4 * 4 + (J)) * 64 + c0; \
    ulonglong2 wA = *(const ulonglong2*)wrow; \
    ulonglong2 wB = *(const ulonglong2*)(wrow + 4); \
    unsigned long long d; \
    d = pack2(X0, X0); \
    acc[0][0] = ffma2(d, wA.x, acc[0][0]); acc[0][1] = ffma2(d, wA.y, acc[0][1]); \
    acc[0][2] = ffma2(d, wB.x, acc[0][2]); acc[0][3] = ffma2(d, wB.y, acc[0][3]); \
    d = pack2(X1, X1); \
    acc[1][0] = ffma2(d, wA.x, acc[1][0]); acc[1][1] = ffma2(d, wA.y, acc[1][1]); \
    acc[1][2] = ffma2(d, wB.x, acc[1][2]); acc[1][3] = ffma2(d, wB.y, acc[1][3]); \
    d = pack2(X2, X2); \
    acc[2][0] = ffma2(d, wA.x, acc[2][0]); acc[2][1] = ffma2(d, wA.y, acc[2][1]); \
    acc[2][2] = ffma2(d, wB.x, acc[2][2]); acc[2][3] = ffma2(d, wB.y, acc[2][3]); \
    d = pack2(X3, X3); \
    acc[3][0] = ffma2(d, wA.x, acc[3][0]); acc[3][1] = ffma2(d, wA.y, acc[3][1]); \
    acc[3][2] = ffma2(d, wB.x, acc[3][2]); acc[3][3] = ffma2(d, wB.y, acc[3][3]); \
}

#pragma unroll 4
    for (int k4 = 0; k4 < 16; k4++) {
        int chunk = k4 ^ (tyg & 7);
        float4 xv0 = ((const float4*)Xs)[(r0 + 0) * 16 + chunk];
        float4 xv1 = ((const float4*)Xs)[(r0 + 1) * 16 + chunk];
        float4 xv2 = ((const float4*)Xs)[(r0 + 2) * 16 + chunk];
        float4 xv3 = ((const float4*)Xs)[(r0 + 3) * 16 + chunk];
        K4BODY(0, xv0.x, xv1.x, xv2.x, xv3.x)
        K4BODY(1, xv0.y, xv1.y, xv2.y, xv3.y)
        K4BODY(2, xv0.z, xv1.z, xv2.z, xv3.z)
        K4BODY(3, xv0.w, xv1.w, xv2.w, xv3.w)
    }
#undef K4BODY

    // ---- epilogue ----
    float4 biaA = *(const float4*)&bia[c0];
    float4 biaB = *(const float4*)&bia[c0 + 4];

    float a[4][8];
    float s1p[4], s2p[4];
#pragma unroll
    for (int i = 0; i < 4; i++) {
        int ci = cats[r0 + i];
        const float* gp = &g_G[(size_t)ci * 64 + c0];
        float4 gA = *(const float4*)gp;
        float4 gB = *(const float4*)(gp + 4);
        unpack2(acc[i][0], a[i][0], a[i][1]);
        unpack2(acc[i][1], a[i][2], a[i][3]);
        unpack2(acc[i][2], a[i][4], a[i][5]);
        unpack2(acc[i][3], a[i][6], a[i][7]);
        a[i][0] += gA.x + biaA.x; a[i][1] += gA.y + biaA.y;
        a[i][2] += gA.z + biaA.z; a[i][3] += gA.w + biaA.w;
        a[i][4] += gB.x + biaB.x; a[i][5] += gB.y + biaB.y;
        a[i][6] += gB.z + biaB.z; a[i][7] += gB.w + biaB.w;
        float s1 = ((a[i][0] + a[i][1]) + (a[i][2] + a[i][3]))
                 + ((a[i][4] + a[i][5]) + (a[i][6] + a[i][7]));
        float s2 = ((a[i][0] * a[i][0] + a[i][1] * a[i][1]) + (a[i][2] * a[i][2] + a[i][3] * a[i][3]))
                 + ((a[i][4] * a[i][4] + a[i][5] * a[i][5]) + (a[i][6] * a[i][6] + a[i][7] * a[i][7]));
        s1 += __shfl_xor_sync(0xffffffffu, s1, 1);
        s2 += __shfl_xor_sync(0xffffffffu, s2, 1);
        s1 += __shfl_xor_sync(0xffffffffu, s1, 2);
        s2 += __shfl_xor_sync(0xffffffffu, s2, 2);
        s1p[i] = s1; s2p[i] = s2;
    }
    if ((l & 3) == 0) {
#pragma unroll
        for (int i = 0; i < 4; i++)
            *(float2*)&sred[(r0 + i) * 4 + (w_ & 1) * 2] = make_float2(s1p[i], s2p[i]);
    }
    __syncthreads();

    float4 gvA = *(const float4*)&gam[c0];
    float4 gvB = *(const float4*)&gam[c0 + 4];
    float4 beA = *(const float4*)&bet[c0];
    float4 beB = *(const float4*)&bet[c0 + 4];
    float csq[8];
#pragma unroll
    for (int j = 0; j < 8; j++) csq[j] = 0.f;

#pragma unroll
    for (int i = 0; i < 4; i++) {
        int rg = base + r0 + i;
        int ci = cats[r0 + i];
        float4 sr = *(const float4*)&sred[(r0 + i) * 4];
        float s1 = sr.x + sr.z, s2 = sr.y + sr.w;
        float mean = s1 * (1.f / 64.f);
        float var  = s2 * (1.f / 64.f) - mean * mean;
        float rs   = rsqrtf(var + 1e-5f);
        float h0 = fmaxf(fmaf((a[i][0] - mean) * rs, gvA.x, beA.x), 0.f);
        float h1 = fmaxf(fmaf((a[i][1] - mean) * rs, gvA.y, beA.y), 0.f);
        float h2 = fmaxf(fmaf((a[i][2] - mean) * rs, gvA.z, beA.z), 0.f);
        float h3 = fmaxf(fmaf((a[i][3] - mean) * rs, gvA.w, beA.w), 0.f);
        float h4 = fmaxf(fmaf((a[i][4] - mean) * rs, gvB.x, beB.x), 0.f);
        float h5 = fmaxf(fmaf((a[i][5] - mean) * rs, gvB.y, beB.y), 0.f);
        float h6 = fmaxf(fmaf((a[i][6] - mean) * rs, gvB.z, beB.z), 0.f);
        float h7 = fmaxf(fmaf((a[i][7] - mean) * rs, gvB.w, beB.w), 0.f);
        if (rg < N) {
            float4* hp = (float4*)&g_H[(size_t)rg * 64 + c0];
            hp[0] = make_float4(h0, h1, h2, h3);
            hp[1] = make_float4(h4, h5, h6, h7);
            float* ap = aggOut + (size_t)ci * 64 + c0;
            float4 curA = *(const float4*)ap;
            float4 curB = *(const float4*)(ap + 4);
            agg_max(ap + 0, h0, curA.x);
            agg_max(ap + 1, h1, curA.y);
            agg_max(ap + 2, h2, curA.z);
            agg_max(ap + 3, h3, curA.w);
            agg_max(ap + 4, h4, curB.x);
            agg_max(ap + 5, h5, curB.y);
            agg_max(ap + 6, h6, curB.z);
            agg_max(ap + 7, h7, curB.w);
            if (COLSQ) {
                csq[0] = fmaf(h0, h0, csq[0]); csq[1] = fmaf(h1, h1, csq[1]);
                csq[2] = fmaf(h2, h2, csq[2]); csq[3] = fmaf(h3, h3, csq[3]);
                csq[4] = fmaf(h4, h4, csq[4]); csq[5] = fmaf(h5, h5, csq[5]);
                csq[6] = fmaf(h6, h6, csq[6]); csq[7] = fmaf(h7, h7, csq[7]);
            }
        }
    }
    if (COLSQ) {
        if (tid < 64) scolsq[tid] = 0.f;
        __syncthreads();
#pragma unroll
        for (int j = 0; j < 8; j++) atomicAdd(&scolsq[c0 + j], csq[j]);
        __syncthreads();
        if (tid < 64) atomicAdd(&g_colsq[tid], scolsq[tid]);
    }
}

// colsq for agg half: sum_s count[s] * agg2[s,j]^2  (L2-hot)
__global__ void k_aggsq(int aggIdx) {
    const float* agg = g_agg + (size_t)aggIdx * NSEG * 64;
    int j = threadIdx.x & 63;
    int sb_ = threadIdx.x >> 6;
    float acc = 0.f;
    for (int s = blockIdx.x * 4 + sb_; s < NSEG; s += gridDim.x * 4) {
        float cnt = (float)g_cnt[s];
        if (cnt > 0.f) {
            float v = agg[(size_t)s * 64 + j];
            acc = fmaf(cnt, v * v, acc);
        }
    }
    __shared__ float red[64];
    if (threadIdx.x < 64) red[threadIdx.x] = 0.f;
    __syncthreads();
    atomicAdd(&red[j], acc);
    __syncthreads();
    if (threadIdx.x < 64) atomicAdd(&g_colsq[64 + threadIdx.x], red[threadIdx.x]);
}

__global__ void k_inv() {
    int j = threadIdx.x;
    if (j < 128) g_inv[j] = 1.f / (sqrtf(g_colsq[j]) + 1e-12f);
}

// out[i] = [h2 | agg2[cat]] * inv_norm  — coalesced: warp = one row,
// thread = one float4 chunk (32 chunks of 4 floats per 128-col row).
__global__ __launch_bounds__(256) void k_scale(
    const void* __restrict__ cat, int aggIdx, float* __restrict__ out, int N)
{
    int gid = blockIdx.x * 256 + threadIdx.x;
    int row = gid >> 5, c4 = gid & 31;
    if (row >= N) return;
    const float* agg = g_agg + (size_t)aggIdx * NSEG * 64;
    float4 v;
    if (c4 < 16) {
        v = ((const float4*)&g_H[(size_t)row * 64])[c4];
    } else {
        int c = get_cat(cat, row, g_is64);
        v = ((const float4*)&agg[(size_t)c * 64])[c4 - 16];
    }
    float4 iv = ((const float4*)g_inv)[c4];
    ((float4*)&out[(size_t)row * 128])[c4] =
        make_float4(v.x * iv.x, v.y * iv.y, v.z * iv.z, v.w * iv.w);
}

// ---------------- launch ----------------
extern "C" void kernel_launch(void* const* d_in, const int* in_sizes, int n_in,
                              void* d_out, int out_size)
{
    const float* x  = (const float*)d_in[0];
    const void*  cat = d_in[1];
    int wb = (in_sizes[2] == 1) ? 3 : 2;
    const float* W0 = (const float*)d_in[wb + 0];
    const float* b0 = (const float*)d_in[wb + 1];
    const float* g0 = (const float*)d_in[wb + 2];
    const float* e0 = (const float*)d_in[wb + 3];
    const float* W1 = (const float*)d_in[wb + 4];
    const float* b1 = (const float*)d_in[wb + 5];
    const float* g1 = (const float*)d_in[wb + 6];
    const float* e1 = (const float*)d_in[wb + 7];
    const float* W2 = (const float*)d_in[wb + 8];
    const float* b2 = (const float*)d_in[wb + 9];
    const float* g2 = (const float*)d_in[wb + 10];
    const float* e2 = (const float*)d_in[wb + 11];

    int N = in_sizes[0] / 8;
    float* out = (float*)d_out;

    cudaFuncSetAttribute(k_layer0, cudaFuncAttributeMaxDynamicSharedMemorySize, L0_SMEM);
    cudaFuncSetAttribute(k_aggmm, cudaFuncAttributeMaxDynamicSharedMemorySize, AMM_SMEM);
    cudaFuncSetAttribute(k_layer<false>, cudaFuncAttributeMaxDynamicSharedMemorySize, SMEM_BYTES);
    cudaFuncSetAttribute(k_layer<true>,  cudaFuncAttributeMaxDynamicSharedMemorySize, SMEM_BYTES);

    int nblk = (N + 127) / 128;
    int nblk_s = (NSEG + 127) / 128;

    k_init<<<8192, 256>>>((const unsigned int*)cat);                 // launch 1
    k_layer0<<<nblk, 256, L0_SMEM>>>(x, cat, W0, b0, g0, e0, N);     // launch 2

    // layer 1: G = agg0 @ W1_bot ; then rows
    k_aggmm<<<nblk_s, 256, AMM_SMEM>>>(0, W1 + 64 * 64);             // launch 3
    k_layer<false><<<nblk, 256, SMEM_BYTES>>>(cat, 1, W1, b1, g1, e1, N);  // launch 4 <- ncu

    // layer 2
    k_aggmm<<<nblk_s, 256, AMM_SMEM>>>(1, W2 + 64 * 64);
    k_layer<true ><<<nblk, 256, SMEM_BYTES>>>(cat, 2, W2, b2, g2, e2, N);

    k_aggsq<<<512, 256>>>(2);
    k_inv<<<1, 128>>>();
    int sc_blocks = (int)(((long long)N * 32 + 255) / 256);
    k_scale<<<sc_blocks, 256>>>(cat, 2, out, N);
}

// round 13
// speedup vs baseline: 1.3391x; 1.0491x over previous
#include <cuda_runtime.h>
#include <cstdint>

// ---------------- static scratch (allocation-free rule) ----------------
#define NSEG 100000
#define NROWS_MAX 2000000

__device__ __align__(16) float g_H[(size_t)NROWS_MAX * 64];      // 512 MB (streaming)
__device__ __align__(16) float g_agg[3u * NSEG * 64];            // 76.8 MB (L2-hot)
__device__ __align__(16) float g_G[(size_t)NSEG * 64];           // 25.6 MB (L2-hot)
__device__ int   g_cnt[NSEG];
__device__ float g_colsq[128];
__device__ float g_inv[128];
__device__ int   g_is64;

// ---------------- f32x2 packed-math helpers (sm_103a) ----------------
__device__ __forceinline__ unsigned long long pack2(float a, float b) {
    unsigned long long r;
    asm("mov.b64 %0, {%1, %2};" : "=l"(r) : "f"(a), "f"(b));
    return r;
}
__device__ __forceinline__ unsigned long long ffma2(unsigned long long a,
                                                    unsigned long long b,
                                                    unsigned long long c) {
    unsigned long long d;
    asm("fma.rn.f32x2 %0, %1, %2, %3;" : "=l"(d) : "l"(a), "l"(b), "l"(c));
    return d;
}
__device__ __forceinline__ void unpack2(unsigned long long v, float& a, float& b) {
    asm("mov.b64 {%0, %1}, %2;" : "=f"(a), "=f"(b) : "l"(v));
}

__device__ __forceinline__ int get_cat(const void* cat, int i, int is64) {
    if (is64) return (int)((const long long*)cat)[i];
    return ((const int*)cat)[i];
}

// filtered float atomicMax for non-negative floats (uint monotone)
__device__ __forceinline__ void agg_max(float* p, float h, float cur) {
    if (h > cur) atomicMax((unsigned int*)p, __float_as_uint(h));
}

// ---------------- kernels ----------------

// init + dtype detect fused (keeps k_layer<false> at launch index 4 for ncu)
__global__ void k_init(const unsigned int* cat) {
    int i = blockIdx.x * blockDim.x + threadIdx.x;
    if (blockIdx.x == 0 && threadIdx.x == 0) {
        int is64 = 1;
        for (int t = 0; t < 64; t++)
            if (cat[2 * t + 1] != 0u) { is64 = 0; break; }
        g_is64 = is64;
    }
    int stride = gridDim.x * blockDim.x;
    float4 z = make_float4(0.f, 0.f, 0.f, 0.f);
    float4* a4 = (float4*)g_agg;
    const int T4 = 3 * NSEG * 64 / 4;
    for (int j = i; j < T4; j += stride) a4[j] = z;
    for (int j = i; j < NSEG; j += stride) g_cnt[j] = 0;
    if (i < 128) g_colsq[i] = 0.f;
}

// ---------------- Layer 0 (tiled, low-reg, 4 CTAs/SM) ----------------
#define L0_XS_BYTES (128 * 8 * 4)        // 4096
#define L0_WS_BYTES (8 * 64 * 4)         // 2048
#define L0_CATS_OFF (L0_XS_BYTES + L0_WS_BYTES)
#define L0_SMEM     (L0_CATS_OFF + 512)

__global__ __launch_bounds__(256, 4) void k_layer0(
    const float* __restrict__ x, const void* __restrict__ cat,
    const float* __restrict__ W, const float* __restrict__ bia,
    const float* __restrict__ gam, const float* __restrict__ bet, int N)
{
    extern __shared__ char smem[];
    float* Xs = (float*)smem;                                   // [128][8]
    const ulonglong2* Wsp = (const ulonglong2*)(smem + L0_XS_BYTES); // [8][16]
    int* cats = (int*)(smem + L0_CATS_OFF);

    int tid = threadIdx.x;
    int base = blockIdx.x * 128;
    int is64 = g_is64;

    if (tid < 128) {
        int r = base + tid;
        int c = (r < N) ? get_cat(cat, r, is64) : 0;
        cats[tid] = c;
        if (r < N) atomicAdd(&g_cnt[c], 1);
    }
    if (tid < 128) {
        ((float4*)(smem + L0_XS_BYTES))[tid] = ((const float4*)W)[tid];
    }
    {
        int r = tid >> 1, c4 = tid & 1;
        int rg = base + r;
        float4 v = make_float4(0.f, 0.f, 0.f, 0.f);
        if (rg < N) v = __ldcs(((const float4*)x) + (size_t)rg * 2 + c4);  // streaming
        ((float4*)Xs)[tid] = v;
    }
    __syncthreads();

    int tx = tid & 15, tyg = tid >> 4;
    int r0 = tyg * 8;

    unsigned long long acc[8][2];
#pragma unroll
    for (int i = 0; i < 8; i++) { acc[i][0] = 0ull; acc[i][1] = 0ull; }

#pragma unroll
    for (int k4 = 0; k4 < 2; k4++) {
        ulonglong2 w0 = Wsp[(k4 * 4 + 0) * 16 + tx];
        ulonglong2 w1 = Wsp[(k4 * 4 + 1) * 16 + tx];
        ulonglong2 w2 = Wsp[(k4 * 4 + 2) * 16 + tx];
        ulonglong2 w3 = Wsp[(k4 * 4 + 3) * 16 + tx];
#pragma unroll
        for (int i = 0; i < 8; i++) {
            float4 xv = ((const float4*)(Xs + (r0 + i) * 8))[k4];
            unsigned long long d;
            d = pack2(xv.x, xv.x);
            acc[i][0] = ffma2(d, w0.x, acc[i][0]); acc[i][1] = ffma2(d, w0.y, acc[i][1]);
            d = pack2(xv.y, xv.y);
            acc[i][0] = ffma2(d, w1.x, acc[i][0]); acc[i][1] = ffma2(d, w1.y, acc[i][1]);
            d = pack2(xv.z, xv.z);
            acc[i][0] = ffma2(d, w2.x, acc[i][0]); acc[i][1] = ffma2(d, w2.y, acc[i][1]);
            d = pack2(xv.w, xv.w);
            acc[i][0] = ffma2(d, w3.x, acc[i][0]); acc[i][1] = ffma2(d, w3.y, acc[i][1]);
        }
    }

    int c0 = tx * 4;
    float4 bv  = *(const float4*)&bia[c0];
    float4 gv  = *(const float4*)&gam[c0];
    float4 bev = *(const float4*)&bet[c0];

    float* agg0 = g_agg;

#pragma unroll
    for (int i = 0; i < 8; i++) {
        int rg = base + r0 + i;
        int ci = cats[r0 + i];
        float4 cur = *(const float4*)(agg0 + (size_t)ci * 64 + c0);
        float a0, a1, a2, a3;
        unpack2(acc[i][0], a0, a1);
        unpack2(acc[i][1], a2, a3);
        a0 += bv.x; a1 += bv.y; a2 += bv.z; a3 += bv.w;
        float s1 = a0 + a1 + a2 + a3;
        float s2 = a0 * a0 + a1 * a1 + a2 * a2 + a3 * a3;
#pragma unroll
        for (int m = 1; m < 16; m <<= 1) {
            s1 += __shfl_xor_sync(0xffffffffu, s1, m);
            s2 += __shfl_xor_sync(0xffffffffu, s2, m);
        }
        float mean = s1 * (1.f / 64.f);
        float var  = s2 * (1.f / 64.f) - mean * mean;
        float rs   = rsqrtf(var + 1e-5f);
        float h0 = fmaxf(fmaf((a0 - mean) * rs, gv.x, bev.x), 0.f);
        float h1 = fmaxf(fmaf((a1 - mean) * rs, gv.y, bev.y), 0.f);
        float h2 = fmaxf(fmaf((a2 - mean) * rs, gv.z, bev.z), 0.f);
        float h3 = fmaxf(fmaf((a3 - mean) * rs, gv.w, bev.w), 0.f);
        if (rg < N) {
            __stcs(((float4*)&g_H[(size_t)rg * 64]) + tx, make_float4(h0, h1, h2, h3));
            float* ap = agg0 + (size_t)ci * 64 + c0;
            agg_max(ap + 0, h0, cur.x);
            agg_max(ap + 1, h1, cur.y);
            agg_max(ap + 2, h2, cur.z);
            agg_max(ap + 3, h3, cur.w);
        }
    }
}

// ---------------- G = agg @ W_bot  (per-segment precompute) ----------------
#define AMM_SMEM (128 * 64 * 4 + 64 * 64 * 4)   // 49152

__global__ __launch_bounds__(256, 3) void k_aggmm(int aggInIdx, const float* __restrict__ Wbot)
{
    extern __shared__ char smem[];
    float* As = (float*)smem;
    const ulonglong2* Wsp = (const ulonglong2*)(smem + 128 * 64 * 4);
    const float* agg = g_agg + (size_t)aggInIdx * NSEG * 64;

    int tid = threadIdx.x;
    int base = blockIdx.x * 128;

    {
        const float4* Wv = (const float4*)Wbot;
        float4* Wd = (float4*)(smem + 128 * 64 * 4);
#pragma unroll
        for (int t = 0; t < 4; t++) Wd[tid + t * 256] = Wv[tid + t * 256];
    }
    {
#pragma unroll
        for (int t = 0; t < 8; t++) {
            int idx = tid + t * 256;
            int r = idx >> 4, c4 = idx & 15;
            int rg = base + r;
            float4 v = make_float4(0.f, 0.f, 0.f, 0.f);
            if (rg < NSEG) v = ((const float4*)&agg[(size_t)rg * 64])[c4];
            ((float4*)&As[r * 64])[c4] = v;
        }
    }
    __syncthreads();

    int tx = tid & 15, tyg = tid >> 4;
    int r0 = tyg * 8;

    unsigned long long acc[8][2];
#pragma unroll
    for (int i = 0; i < 8; i++) { acc[i][0] = 0ull; acc[i][1] = 0ull; }

#pragma unroll 4
    for (int k4 = 0; k4 < 16; k4++) {
        ulonglong2 w0 = Wsp[(k4 * 4 + 0) * 16 + tx];
        ulonglong2 w1 = Wsp[(k4 * 4 + 1) * 16 + tx];
        ulonglong2 w2 = Wsp[(k4 * 4 + 2) * 16 + tx];
        ulonglong2 w3 = Wsp[(k4 * 4 + 3) * 16 + tx];
#pragma unroll
        for (int i = 0; i < 8; i++) {
            float4 xv = ((const float4*)(As + (r0 + i) * 64))[k4];
            unsigned long long d;
            d = pack2(xv.x, xv.x);
            acc[i][0] = ffma2(d, w0.x, acc[i][0]); acc[i][1] = ffma2(d, w0.y, acc[i][1]);
            d = pack2(xv.y, xv.y);
            acc[i][0] = ffma2(d, w1.x, acc[i][0]); acc[i][1] = ffma2(d, w1.y, acc[i][1]);
            d = pack2(xv.z, xv.z);
            acc[i][0] = ffma2(d, w2.x, acc[i][0]); acc[i][1] = ffma2(d, w2.y, acc[i][1]);
            d = pack2(xv.w, xv.w);
            acc[i][0] = ffma2(d, w3.x, acc[i][0]); acc[i][1] = ffma2(d, w3.y, acc[i][1]);
        }
    }

    int c0 = tx * 4;
#pragma unroll
    for (int i = 0; i < 8; i++) {
        int rg = base + r0 + i;
        if (rg < NSEG) {
            float a0, a1, a2, a3;
            unpack2(acc[i][0], a0, a1);
            unpack2(acc[i][1], a2, a3);
            *(float4*)&g_G[(size_t)rg * 64 + c0] = make_float4(a0, a1, a2, a3);
        }
    }
}

// ---------------- Layers 1/2 (round-7 balanced warp tile — best measured) ---
// 256 threads; thread tile 4 rows x 8 cols.
//   txg = (w&1)*4 | (l&3)   (8 col-groups of 8)
//   tyg = (w>>1)*8 | (l>>2) (32 row-groups of 4)
// Xs chunk-swizzled: logical chunk c4 of row r stored at c4 ^ ((r>>2)&7).
#define XS_BYTES  (128 * 64 * 4)                 // 32768
#define WS_BYTES  (64 * 64 * 4)                  // 16384
#define CATS_OFF  (XS_BYTES + WS_BYTES)          // 49152
#define SRED_OFF  (CATS_OFF + 512)               // 49664
#define SCSQ_OFF  (SRED_OFF + 128 * 16)          // 51712
#define SMEM_BYTES (SCSQ_OFF + 256)              // 51968

template <bool COLSQ>
__global__ __launch_bounds__(256, 3) void k_layer(
    const void* __restrict__ cat, int aggOutIdx,
    const float* __restrict__ Wtop, const float* __restrict__ bia,
    const float* __restrict__ gam, const float* __restrict__ bet, int N)
{
    extern __shared__ char smem[];
    float* Xs = (float*)smem;                                  // [128][64] swizzled
    const float* Ws = (const float*)(smem + XS_BYTES);         // [64][64]
    int* cats = (int*)(smem + CATS_OFF);
    float* sred = (float*)(smem + SRED_OFF);                   // [128][4]
    float* scolsq = (float*)(smem + SCSQ_OFF);

    float* aggOut = g_agg + (size_t)aggOutIdx * NSEG * 64;

    int tid = threadIdx.x;
    int base = blockIdx.x * 128;
    int is64 = g_is64;
    int w_ = tid >> 5, l = tid & 31;

    if (tid < 128) {
        int r = base + tid;
        cats[tid] = (r < N) ? get_cat(cat, r, is64) : 0;
    }
    {   // W_top: 1024 float4 (plain layout)
        const float4* Wv = (const float4*)Wtop;
        float4* Wd = (float4*)(smem + XS_BYTES);
#pragma unroll
        for (int t = 0; t < 4; t++) Wd[tid + t * 256] = Wv[tid + t * 256];
    }
    {   // Xs = H tile: 2048 float4, chunk-swizzled per row (streaming loads)
#pragma unroll
        for (int t = 0; t < 8; t++) {
            int idx = tid + t * 256;
            int r = idx >> 4, c4 = idx & 15;
            int rg = base + r;
            float4 v = make_float4(0.f, 0.f, 0.f, 0.f);
            if (rg < N) v = __ldcs(((const float4*)&g_H[(size_t)rg * 64]) + c4);
            ((float4*)Xs)[r * 16 + (c4 ^ ((r >> 2) & 7))] = v;
        }
    }
    __syncthreads();

    int txg = ((w_ & 1) << 2) | (l & 3);     // 0..7
    int tyg = ((w_ >> 1) << 3) | (l >> 2);   // 0..31
    int r0 = tyg * 4;
    int c0 = txg * 8;

    unsigned long long acc[4][4];
#pragma unroll
    for (int i = 0; i < 4; i++)
#pragma unroll
        for (int c = 0; c < 4; c++) acc[i][c] = 0ull;

#define K4BODY(J, X0, X1, X2, X3) { \
    const float* wrow = Ws + (k4 * 4 + (J)) * 64 + c0; \
    ulonglong2 wA = *(const ulonglong2*)wrow; \
    ulonglong2 wB = *(const ulonglong2*)(wrow + 4); \
    unsigned long long d; \
    d = pack2(X0, X0); \
    acc[0][0] = ffma2(d, wA.x, acc[0][0]); acc[0][1] = ffma2(d, wA.y, acc[0][1]); \
    acc[0][2] = ffma2(d, wB.x, acc[0][2]); acc[0][3] = ffma2(d, wB.y, acc[0][3]); \
    d = pack2(X1, X1); \
    acc[1][0] = ffma2(d, wA.x, acc[1][0]); acc[1][1] = ffma2(d, wA.y, acc[1][1]); \
    acc[1][2] = ffma2(d, wB.x, acc[1][2]); acc[1][3] = ffma2(d, wB.y, acc[1][3]); \
    d = pack2(X2, X2); \
    acc[2][0] = ffma2(d, wA.x, acc[2][0]); acc[2][1] = ffma2(d, wA.y, acc[2][1]); \
    acc[2][2] = ffma2(d, wB.x, acc[2][2]); acc[2][3] = ffma2(d, wB.y, acc[2][3]); \
    d = pack2(X3, X3); \
    acc[3][0] = ffma2(d, wA.x, acc[3][0]); acc[3][1] = ffma2(d, wA.y, acc[3][1]); \
    acc[3][2] = ffma2(d, wB.x, acc[3][2]); acc[3][3] = ffma2(d, wB.y, acc[3][3]); \
}

#pragma unroll 4
    for (int k4 = 0; k4 < 16; k4++) {
        int chunk = k4 ^ (tyg & 7);
        float4 xv0 = ((const float4*)Xs)[(r0 + 0) * 16 + chunk];
        float4 xv1 = ((const float4*)Xs)[(r0 + 1) * 16 + chunk];
        float4 xv2 = ((const float4*)Xs)[(r0 + 2) * 16 + chunk];
        float4 xv3 = ((const float4*)Xs)[(r0 + 3) * 16 + chunk];
        K4BODY(0, xv0.x, xv1.x, xv2.x, xv3.x)
        K4BODY(1, xv0.y, xv1.y, xv2.y, xv3.y)
        K4BODY(2, xv0.z, xv1.z, xv2.z, xv3.z)
        K4BODY(3, xv0.w, xv1.w, xv2.w, xv3.w)
    }
#undef K4BODY

    // ---- epilogue ----
    float4 biaA = *(const float4*)&bia[c0];
    float4 biaB = *(const float4*)&bia[c0 + 4];

    float a[4][8];
    float s1p[4], s2p[4];
#pragma unroll
    for (int i = 0; i < 4; i++) {
        int ci = cats[r0 + i];
        const float* gp = &g_G[(size_t)ci * 64 + c0];
        float4 gA = *(const float4*)gp;
        float4 gB = *(const float4*)(gp + 4);
        unpack2(acc[i][0], a[i][0], a[i][1]);
        unpack2(acc[i][1], a[i][2], a[i][3]);
        unpack2(acc[i][2], a[i][4], a[i][5]);
        unpack2(acc[i][3], a[i][6], a[i][7]);
        a[i][0] += gA.x + biaA.x; a[i][1] += gA.y + biaA.y;
        a[i][2] += gA.z + biaA.z; a[i][3] += gA.w + biaA.w;
        a[i][4] += gB.x + biaB.x; a[i][5] += gB.y + biaB.y;
        a[i][6] += gB.z + biaB.z; a[i][7] += gB.w + biaB.w;
        float s1 = ((a[i][0] + a[i][1]) + (a[i][2] + a[i][3]))
                 + ((a[i][4] + a[i][5]) + (a[i][6] + a[i][7]));
        float s2 = ((a[i][0] * a[i][0] + a[i][1] * a[i][1]) + (a[i][2] * a[i][2] + a[i][3] * a[i][3]))
                 + ((a[i][4] * a[i][4] + a[i][5] * a[i][5]) + (a[i][6] * a[i][6] + a[i][7] * a[i][7]));
        s1 += __shfl_xor_sync(0xffffffffu, s1, 1);
        s2 += __shfl_xor_sync(0xffffffffu, s2, 1);
        s1 += __shfl_xor_sync(0xffffffffu, s1, 2);
        s2 += __shfl_xor_sync(0xffffffffu, s2, 2);
        s1p[i] = s1; s2p[i] = s2;
    }
    if ((l & 3) == 0) {
#pragma unroll
        for (int i = 0; i < 4; i++)
            *(float2*)&sred[(r0 + i) * 4 + (w_ & 1) * 2] = make_float2(s1p[i], s2p[i]);
    }
    __syncthreads();

    float4 gvA = *(const float4*)&gam[c0];
    float4 gvB = *(const float4*)&gam[c0 + 4];
    float4 beA = *(const float4*)&bet[c0];
    float4 beB = *(const float4*)&bet[c0 + 4];
    float csq[8];
#pragma unroll
    for (int j = 0; j < 8; j++) csq[j] = 0.f;

#pragma unroll
    for (int i = 0; i < 4; i++) {
        int rg = base + r0 + i;
        int ci = cats[r0 + i];
        float4 sr = *(const float4*)&sred[(r0 + i) * 4];
        float s1 = sr.x + sr.z, s2 = sr.y + sr.w;
        float mean = s1 * (1.f / 64.f);
        float var  = s2 * (1.f / 64.f) - mean * mean;
        float rs   = rsqrtf(var + 1e-5f);
        float h0 = fmaxf(fmaf((a[i][0] - mean) * rs, gvA.x, beA.x), 0.f);
        float h1 = fmaxf(fmaf((a[i][1] - mean) * rs, gvA.y, beA.y), 0.f);
        float h2 = fmaxf(fmaf((a[i][2] - mean) * rs, gvA.z, beA.z), 0.f);
        float h3 = fmaxf(fmaf((a[i][3] - mean) * rs, gvA.w, beA.w), 0.f);
        float h4 = fmaxf(fmaf((a[i][4] - mean) * rs, gvB.x, beB.x), 0.f);
        float h5 = fmaxf(fmaf((a[i][5] - mean) * rs, gvB.y, beB.y), 0.f);
        float h6 = fmaxf(fmaf((a[i][6] - mean) * rs, gvB.z, beB.z), 0.f);
        float h7 = fmaxf(fmaf((a[i][7] - mean) * rs, gvB.w, beB.w), 0.f);
        if (rg < N) {
            float4* hp = (float4*)&g_H[(size_t)rg * 64 + c0];
            __stcs(hp,     make_float4(h0, h1, h2, h3));
            __stcs(hp + 1, make_float4(h4, h5, h6, h7));
            float* ap = aggOut + (size_t)ci * 64 + c0;
            float4 curA = *(const float4*)ap;
            float4 curB = *(const float4*)(ap + 4);
            agg_max(ap + 0, h0, curA.x);
            agg_max(ap + 1, h1, curA.y);
            agg_max(ap + 2, h2, curA.z);
            agg_max(ap + 3, h3, curA.w);
            agg_max(ap + 4, h4, curB.x);
            agg_max(ap + 5, h5, curB.y);
            agg_max(ap + 6, h6, curB.z);
            agg_max(ap + 7, h7, curB.w);
            if (COLSQ) {
                csq[0] = fmaf(h0, h0, csq[0]); csq[1] = fmaf(h1, h1, csq[1]);
                csq[2] = fmaf(h2, h2, csq[2]); csq[3] = fmaf(h3, h3, csq[3]);
                csq[4] = fmaf(h4, h4, csq[4]); csq[5] = fmaf(h5, h5, csq[5]);
                csq[6] = fmaf(h6, h6, csq[6]); csq[7] = fmaf(h7, h7, csq[7]);
            }
        }
    }
    if (COLSQ) {
        if (tid < 64) scolsq[tid] = 0.f;
        __syncthreads();
#pragma unroll
        for (int j = 0; j < 8; j++) atomicAdd(&scolsq[c0 + j], csq[j]);
        __syncthreads();
        if (tid < 64) atomicAdd(&g_colsq[tid], scolsq[tid]);
    }
}

// colsq for agg half: sum_s count[s] * agg2[s,j]^2  (L2-hot)
__global__ void k_aggsq(int aggIdx) {
    const float* agg = g_agg + (size_t)aggIdx * NSEG * 64;
    int j = threadIdx.x & 63;
    int sb_ = threadIdx.x >> 6;
    float acc = 0.f;
    for (int s = blockIdx.x * 4 + sb_; s < NSEG; s += gridDim.x * 4) {
        float cnt = (float)g_cnt[s];
        if (cnt > 0.f) {
            float v = agg[(size_t)s * 64 + j];
            acc = fmaf(cnt, v * v, acc);
        }
    }
    __shared__ float red[64];
    if (threadIdx.x < 64) red[threadIdx.x] = 0.f;
    __syncthreads();
    atomicAdd(&red[j], acc);
    __syncthreads();
    if (threadIdx.x < 64) atomicAdd(&g_colsq[64 + threadIdx.x], red[threadIdx.x]);
}

__global__ void k_inv() {
    int j = threadIdx.x;
    if (j < 128) g_inv[j] = 1.f / (sqrtf(g_colsq[j]) + 1e-12f);
}

// out[i] = [h2 | agg2[cat]] * inv_norm  — coalesced: warp = one row,
// thread = one float4 chunk (32 chunks of 4 floats per 128-col row).
__global__ __launch_bounds__(256) void k_scale(
    const void* __restrict__ cat, int aggIdx, float* __restrict__ out, int N)
{
    int gid = blockIdx.x * 256 + threadIdx.x;
    int row = gid >> 5, c4 = gid & 31;
    if (row >= N) return;
    const float* agg = g_agg + (size_t)aggIdx * NSEG * 64;
    float4 v;
    if (c4 < 16) {
        v = __ldcs(((const float4*)&g_H[(size_t)row * 64]) + c4);   // streaming
    } else {
        int c = get_cat(cat, row, g_is64);
        v = ((const float4*)&agg[(size_t)c * 64])[c4 - 16];         // L2-hot
    }
    float4 iv = ((const float4*)g_inv)[c4];
    __stcs(((float4*)&out[(size_t)row * 128]) + c4,
           make_float4(v.x * iv.x, v.y * iv.y, v.z * iv.z, v.w * iv.w));
}

// ---------------- launch ----------------
extern "C" void kernel_launch(void* const* d_in, const int* in_sizes, int n_in,
                              void* d_out, int out_size)
{
    const float* x  = (const float*)d_in[0];
    const void*  cat = d_in[1];
    int wb = (in_sizes[2] == 1) ? 3 : 2;
    const float* W0 = (const float*)d_in[wb + 0];
    const float* b0 = (const float*)d_in[wb + 1];
    const float* g0 = (const float*)d_in[wb + 2];
    const float* e0 = (const float*)d_in[wb + 3];
    const float* W1 = (const float*)d_in[wb + 4];
    const float* b1 = (const float*)d_in[wb + 5];
    const float* g1 = (const float*)d_in[wb + 6];
    const float* e1 = (const float*)d_in[wb + 7];
    const float* W2 = (const float*)d_in[wb + 8];
    const float* b2 = (const float*)d_in[wb + 9];
    const float* g2 = (const float*)d_in[wb + 10];
    const float* e2 = (const float*)d_in[wb + 11];

    int N = in_sizes[0] / 8;
    float* out = (float*)d_out;

    cudaFuncSetAttribute(k_layer0, cudaFuncAttributeMaxDynamicSharedMemorySize, L0_SMEM);
    cudaFuncSetAttribute(k_aggmm, cudaFuncAttributeMaxDynamicSharedMemorySize, AMM_SMEM);
    cudaFuncSetAttribute(k_layer<false>, cudaFuncAttributeMaxDynamicSharedMemorySize, SMEM_BYTES);
    cudaFuncSetAttribute(k_layer<true>,  cudaFuncAttributeMaxDynamicSharedMemorySize, SMEM_BYTES);

    int nblk = (N + 127) / 128;
    int nblk_s = (NSEG + 127) / 128;

    k_init<<<8192, 256>>>((const unsigned int*)cat);                 // launch 1
    k_layer0<<<nblk, 256, L0_SMEM>>>(x, cat, W0, b0, g0, e0, N);     // launch 2

    // layer 1: G = agg0 @ W1_bot ; then rows
    k_aggmm<<<nblk_s, 256, AMM_SMEM>>>(0, W1 + 64 * 64);             // launch 3
    k_layer<false><<<nblk, 256, SMEM_BYTES>>>(cat, 1, W1, b1, g1, e1, N);  // launch 4 <- ncu

    // layer 2
    k_aggmm<<<nblk_s, 256, AMM_SMEM>>>(1, W2 + 64 * 64);
    k_layer<true ><<<nblk, 256, SMEM_BYTES>>>(cat, 2, W2, b2, g2, e2, N);

    k_aggsq<<<512, 256>>>(2);
    k_inv<<<1, 128>>>();
    int sc_blocks = (int)(((long long)N * 32 + 255) / 256);
    k_scale<<<sc_blocks, 256>>>(cat, 2, out, N);
}

// round 14
// speedup vs baseline: 1.3961x; 1.0426x over previous
#include <cuda_runtime.h>
#include <cstdint>

// ---------------- static scratch (allocation-free rule) ----------------
#define NSEG 100000
#define NROWS_MAX 2000000

__device__ __align__(16) float g_H[(size_t)NROWS_MAX * 64];      // 512 MB (streaming)
__device__ __align__(16) float g_agg[3u * NSEG * 64];            // 76.8 MB (L2-hot)
__device__ __align__(16) float g_G[(size_t)NSEG * 64];           // 25.6 MB (L2-hot)
__device__ int   g_cnt[NSEG];
__device__ float g_colsq[128];
__device__ float g_inv[128];
__device__ int   g_is64;

// ---------------- f32x2 packed-math helpers (sm_103a) ----------------
__device__ __forceinline__ unsigned long long pack2(float a, float b) {
    unsigned long long r;
    asm("mov.b64 %0, {%1, %2};" : "=l"(r) : "f"(a), "f"(b));
    return r;
}
__device__ __forceinline__ unsigned long long ffma2(unsigned long long a,
                                                    unsigned long long b,
                                                    unsigned long long c) {
    unsigned long long d;
    asm("fma.rn.f32x2 %0, %1, %2, %3;" : "=l"(d) : "l"(a), "l"(b), "l"(c));
    return d;
}
__device__ __forceinline__ void unpack2(unsigned long long v, float& a, float& b) {
    asm("mov.b64 {%0, %1}, %2;" : "=f"(a), "=f"(b) : "l"(v));
}

__device__ __forceinline__ int get_cat(const void* cat, int i, int is64) {
    if (is64) return (int)((const long long*)cat)[i];
    return ((const int*)cat)[i];
}

// filtered float atomicMax for non-negative floats (uint monotone)
__device__ __forceinline__ void agg_max(float* p, float h, float cur) {
    if (h > cur) atomicMax((unsigned int*)p, __float_as_uint(h));
}

// ---------------- kernels ----------------

// init + dtype detect fused (keeps k_layer<false> at launch index 4 for ncu)
__global__ void k_init(const unsigned int* cat) {
    int i = blockIdx.x * blockDim.x + threadIdx.x;
    if (blockIdx.x == 0 && threadIdx.x == 0) {
        int is64 = 1;
        for (int t = 0; t < 64; t++)
            if (cat[2 * t + 1] != 0u) { is64 = 0; break; }
        g_is64 = is64;
    }
    int stride = gridDim.x * blockDim.x;
    float4 z = make_float4(0.f, 0.f, 0.f, 0.f);
    float4* a4 = (float4*)g_agg;
    const int T4 = 3 * NSEG * 64 / 4;
    for (int j = i; j < T4; j += stride) a4[j] = z;
    for (int j = i; j < NSEG; j += stride) g_cnt[j] = 0;
    if (i < 128) g_colsq[i] = 0.f;
}

// ---------------- Layer 0 (tiled, low-reg, 4 CTAs/SM) ----------------
#define L0_XS_BYTES (128 * 8 * 4)        // 4096
#define L0_WS_BYTES (8 * 64 * 4)         // 2048
#define L0_CATS_OFF (L0_XS_BYTES + L0_WS_BYTES)
#define L0_SMEM     (L0_CATS_OFF + 512)

__global__ __launch_bounds__(256, 4) void k_layer0(
    const float* __restrict__ x, const void* __restrict__ cat,
    const float* __restrict__ W, const float* __restrict__ bia,
    const float* __restrict__ gam, const float* __restrict__ bet, int N)
{
    extern __shared__ char smem[];
    float* Xs = (float*)smem;                                   // [128][8]
    const ulonglong2* Wsp = (const ulonglong2*)(smem + L0_XS_BYTES); // [8][16]
    int* cats = (int*)(smem + L0_CATS_OFF);

    int tid = threadIdx.x;
    int base = blockIdx.x * 128;
    int is64 = g_is64;

    if (tid < 128) {
        int r = base + tid;
        int c = (r < N) ? get_cat(cat, r, is64) : 0;
        cats[tid] = c;
        if (r < N) atomicAdd(&g_cnt[c], 1);
    }
    if (tid < 128) {
        ((float4*)(smem + L0_XS_BYTES))[tid] = ((const float4*)W)[tid];
    }
    {
        int r = tid >> 1, c4 = tid & 1;
        int rg = base + r;
        float4 v = make_float4(0.f, 0.f, 0.f, 0.f);
        if (rg < N) v = __ldcs(((const float4*)x) + (size_t)rg * 2 + c4);  // streaming
        ((float4*)Xs)[tid] = v;
    }
    __syncthreads();

    int tx = tid & 15, tyg = tid >> 4;
    int r0 = tyg * 8;

    unsigned long long acc[8][2];
#pragma unroll
    for (int i = 0; i < 8; i++) { acc[i][0] = 0ull; acc[i][1] = 0ull; }

#pragma unroll
    for (int k4 = 0; k4 < 2; k4++) {
        ulonglong2 w0 = Wsp[(k4 * 4 + 0) * 16 + tx];
        ulonglong2 w1 = Wsp[(k4 * 4 + 1) * 16 + tx];
        ulonglong2 w2 = Wsp[(k4 * 4 + 2) * 16 + tx];
        ulonglong2 w3 = Wsp[(k4 * 4 + 3) * 16 + tx];
#pragma unroll
        for (int i = 0; i < 8; i++) {
            float4 xv = ((const float4*)(Xs + (r0 + i) * 8))[k4];
            unsigned long long d;
            d = pack2(xv.x, xv.x);
            acc[i][0] = ffma2(d, w0.x, acc[i][0]); acc[i][1] = ffma2(d, w0.y, acc[i][1]);
            d = pack2(xv.y, xv.y);
            acc[i][0] = ffma2(d, w1.x, acc[i][0]); acc[i][1] = ffma2(d, w1.y, acc[i][1]);
            d = pack2(xv.z, xv.z);
            acc[i][0] = ffma2(d, w2.x, acc[i][0]); acc[i][1] = ffma2(d, w2.y, acc[i][1]);
            d = pack2(xv.w, xv.w);
            acc[i][0] = ffma2(d, w3.x, acc[i][0]); acc[i][1] = ffma2(d, w3.y, acc[i][1]);
        }
    }

    int c0 = tx * 4;
    float4 bv  = *(const float4*)&bia[c0];
    float4 gv  = *(const float4*)&gam[c0];
    float4 bev = *(const float4*)&bet[c0];

    float* agg0 = g_agg;

#pragma unroll
    for (int i = 0; i < 8; i++) {
        int rg = base + r0 + i;
        int ci = cats[r0 + i];
        float4 cur = *(const float4*)(agg0 + (size_t)ci * 64 + c0);
        float a0, a1, a2, a3;
        unpack2(acc[i][0], a0, a1);
        unpack2(acc[i][1], a2, a3);
        a0 += bv.x; a1 += bv.y; a2 += bv.z; a3 += bv.w;
        float s1 = a0 + a1 + a2 + a3;
        float s2 = a0 * a0 + a1 * a1 + a2 * a2 + a3 * a3;
#pragma unroll
        for (int m = 1; m < 16; m <<= 1) {
            s1 += __shfl_xor_sync(0xffffffffu, s1, m);
            s2 += __shfl_xor_sync(0xffffffffu, s2, m);
        }
        float mean = s1 * (1.f / 64.f);
        float var  = s2 * (1.f / 64.f) - mean * mean;
        float rs   = rsqrtf(var + 1e-5f);
        float h0 = fmaxf(fmaf((a0 - mean) * rs, gv.x, bev.x), 0.f);
        float h1 = fmaxf(fmaf((a1 - mean) * rs, gv.y, bev.y), 0.f);
        float h2 = fmaxf(fmaf((a2 - mean) * rs, gv.z, bev.z), 0.f);
        float h3 = fmaxf(fmaf((a3 - mean) * rs, gv.w, bev.w), 0.f);
        if (rg < N) {
            __stcs(((float4*)&g_H[(size_t)rg * 64]) + tx, make_float4(h0, h1, h2, h3));
            float* ap = agg0 + (size_t)ci * 64 + c0;
            agg_max(ap + 0, h0, cur.x);
            agg_max(ap + 1, h1, cur.y);
            agg_max(ap + 2, h2, cur.z);
            agg_max(ap + 3, h3, cur.w);
        }
    }
}

// ---------------- G = agg @ W_bot  (per-segment precompute) ----------------
#define AMM_SMEM (128 * 64 * 4 + 64 * 64 * 4)   // 49152

__global__ __launch_bounds__(256, 3) void k_aggmm(int aggInIdx, const float* __restrict__ Wbot)
{
    extern __shared__ char smem[];
    float* As = (float*)smem;
    const ulonglong2* Wsp = (const ulonglong2*)(smem + 128 * 64 * 4);
    const float* agg = g_agg + (size_t)aggInIdx * NSEG * 64;

    int tid = threadIdx.x;
    int base = blockIdx.x * 128;

    {
        const float4* Wv = (const float4*)Wbot;
        float4* Wd = (float4*)(smem + 128 * 64 * 4);
#pragma unroll
        for (int t = 0; t < 4; t++) Wd[tid + t * 256] = Wv[tid + t * 256];
    }
    {
#pragma unroll
        for (int t = 0; t < 8; t++) {
            int idx = tid + t * 256;
            int r = idx >> 4, c4 = idx & 15;
            int rg = base + r;
            float4 v = make_float4(0.f, 0.f, 0.f, 0.f);
            if (rg < NSEG) v = ((const float4*)&agg[(size_t)rg * 64])[c4];
            ((float4*)&As[r * 64])[c4] = v;
        }
    }
    __syncthreads();

    int tx = tid & 15, tyg = tid >> 4;
    int r0 = tyg * 8;

    unsigned long long acc[8][2];
#pragma unroll
    for (int i = 0; i < 8; i++) { acc[i][0] = 0ull; acc[i][1] = 0ull; }

#pragma unroll 4
    for (int k4 = 0; k4 < 16; k4++) {
        ulonglong2 w0 = Wsp[(k4 * 4 + 0) * 16 + tx];
        ulonglong2 w1 = Wsp[(k4 * 4 + 1) * 16 + tx];
        ulonglong2 w2 = Wsp[(k4 * 4 + 2) * 16 + tx];
        ulonglong2 w3 = Wsp[(k4 * 4 + 3) * 16 + tx];
#pragma unroll
        for (int i = 0; i < 8; i++) {
            float4 xv = ((const float4*)(As + (r0 + i) * 64))[k4];
            unsigned long long d;
            d = pack2(xv.x, xv.x);
            acc[i][0] = ffma2(d, w0.x, acc[i][0]); acc[i][1] = ffma2(d, w0.y, acc[i][1]);
            d = pack2(xv.y, xv.y);
            acc[i][0] = ffma2(d, w1.x, acc[i][0]); acc[i][1] = ffma2(d, w1.y, acc[i][1]);
            d = pack2(xv.z, xv.z);
            acc[i][0] = ffma2(d, w2.x, acc[i][0]); acc[i][1] = ffma2(d, w2.y, acc[i][1]);
            d = pack2(xv.w, xv.w);
            acc[i][0] = ffma2(d, w3.x, acc[i][0]); acc[i][1] = ffma2(d, w3.y, acc[i][1]);
        }
    }

    int c0 = tx * 4;
#pragma unroll
    for (int i = 0; i < 8; i++) {
        int rg = base + r0 + i;
        if (rg < NSEG) {
            float a0, a1, a2, a3;
            unpack2(acc[i][0], a0, a1);
            unpack2(acc[i][1], a2, a3);
            *(float4*)&g_G[(size_t)rg * 64 + c0] = make_float4(a0, a1, a2, a3);
        }
    }
}

// ---------------- Layers 1/2 (round-7 balanced warp tile — best measured) ---
#define XS_BYTES  (128 * 64 * 4)                 // 32768
#define WS_BYTES  (64 * 64 * 4)                  // 16384
#define CATS_OFF  (XS_BYTES + WS_BYTES)          // 49152
#define SRED_OFF  (CATS_OFF + 512)               // 49664
#define SCSQ_OFF  (SRED_OFF + 128 * 16)          // 51712
#define SMEM_BYTES (SCSQ_OFF + 256)              // 51968

template <bool COLSQ>
__global__ __launch_bounds__(256, 3) void k_layer(
    const void* __restrict__ cat, int aggOutIdx,
    const float* __restrict__ Wtop, const float* __restrict__ bia,
    const float* __restrict__ gam, const float* __restrict__ bet, int N)
{
    extern __shared__ char smem[];
    float* Xs = (float*)smem;                                  // [128][64] swizzled
    const float* Ws = (const float*)(smem + XS_BYTES);         // [64][64]
    int* cats = (int*)(smem + CATS_OFF);
    float* sred = (float*)(smem + SRED_OFF);                   // [128][4]
    float* scolsq = (float*)(smem + SCSQ_OFF);

    float* aggOut = g_agg + (size_t)aggOutIdx * NSEG * 64;

    int tid = threadIdx.x;
    int base = blockIdx.x * 128;
    int is64 = g_is64;
    int w_ = tid >> 5, l = tid & 31;

    if (tid < 128) {
        int r = base + tid;
        cats[tid] = (r < N) ? get_cat(cat, r, is64) : 0;
    }
    {   // W_top: 1024 float4 (plain layout)
        const float4* Wv = (const float4*)Wtop;
        float4* Wd = (float4*)(smem + XS_BYTES);
#pragma unroll
        for (int t = 0; t < 4; t++) Wd[tid + t * 256] = Wv[tid + t * 256];
    }
    {   // Xs = H tile: 2048 float4, chunk-swizzled per row (streaming loads)
#pragma unroll
        for (int t = 0; t < 8; t++) {
            int idx = tid + t * 256;
            int r = idx >> 4, c4 = idx & 15;
            int rg = base + r;
            float4 v = make_float4(0.f, 0.f, 0.f, 0.f);
            if (rg < N) v = __ldcs(((const float4*)&g_H[(size_t)rg * 64]) + c4);
            ((float4*)Xs)[r * 16 + (c4 ^ ((r >> 2) & 7))] = v;
        }
    }
    __syncthreads();

    int txg = ((w_ & 1) << 2) | (l & 3);     // 0..7
    int tyg = ((w_ >> 1) << 3) | (l >> 2);   // 0..31
    int r0 = tyg * 4;
    int c0 = txg * 8;

    unsigned long long acc[4][4];
#pragma unroll
    for (int i = 0; i < 4; i++)
#pragma unroll
        for (int c = 0; c < 4; c++) acc[i][c] = 0ull;

#define K4BODY(J, X0, X1, X2, X3) { \
    const float* wrow = Ws + (k4 * 4 + (J)) * 64 + c0; \
    ulonglong2 wA = *(const ulonglong2*)wrow; \
    ulonglong2 wB = *(const ulonglong2*)(wrow + 4); \
    unsigned long long d; \
    d = pack2(X0, X0); \
    acc[0][0] = ffma2(d, wA.x, acc[0][0]); acc[0][1] = ffma2(d, wA.y, acc[0][1]); \
    acc[0][2] = ffma2(d, wB.x, acc[0][2]); acc[0][3] = ffma2(d, wB.y, acc[0][3]); \
    d = pack2(X1, X1); \
    acc[1][0] = ffma2(d, wA.x, acc[1][0]); acc[1][1] = ffma2(d, wA.y, acc[1][1]); \
    acc[1][2] = ffma2(d, wB.x, acc[1][2]); acc[1][3] = ffma2(d, wB.y, acc[1][3]); \
    d = pack2(X2, X2); \
    acc[2][0] = ffma2(d, wA.x, acc[2][0]); acc[2][1] = ffma2(d, wA.y, acc[2][1]); \
    acc[2][2] = ffma2(d, wB.x, acc[2][2]); acc[2][3] = ffma2(d, wB.y, acc[2][3]); \
    d = pack2(X3, X3); \
    acc[3][0] = ffma2(d, wA.x, acc[3][0]); acc[3][1] = ffma2(d, wA.y, acc[3][1]); \
    acc[3][2] = ffma2(d, wB.x, acc[3][2]); acc[3][3] = ffma2(d, wB.y, acc[3][3]); \
}

#pragma unroll 4
    for (int k4 = 0; k4 < 16; k4++) {
        int chunk = k4 ^ (tyg & 7);
        float4 xv0 = ((const float4*)Xs)[(r0 + 0) * 16 + chunk];
        float4 xv1 = ((const float4*)Xs)[(r0 + 1) * 16 + chunk];
        float4 xv2 = ((const float4*)Xs)[(r0 + 2) * 16 + chunk];
        float4 xv3 = ((const float4*)Xs)[(r0 + 3) * 16 + chunk];
        K4BODY(0, xv0.x, xv1.x, xv2.x, xv3.x)
        K4BODY(1, xv0.y, xv1.y, xv2.y, xv3.y)
        K4BODY(2, xv0.z, xv1.z, xv2.z, xv3.z)
        K4BODY(3, xv0.w, xv1.w, xv2.w, xv3.w)
    }
#undef K4BODY

    // ---- epilogue ----
    float4 biaA = *(const float4*)&bia[c0];
    float4 biaB = *(const float4*)&bia[c0 + 4];

    float a[4][8];
    float s1p[4], s2p[4];
#pragma unroll
    for (int i = 0; i < 4; i++) {
        int ci = cats[r0 + i];
        const float* gp = &g_G[(size_t)ci * 64 + c0];
        float4 gA = *(const float4*)gp;
        float4 gB = *(const float4*)(gp + 4);
        unpack2(acc[i][0], a[i][0], a[i][1]);
        unpack2(acc[i][1], a[i][2], a[i][3]);
        unpack2(acc[i][2], a[i][4], a[i][5]);
        unpack2(acc[i][3], a[i][6], a[i][7]);
        a[i][0] += gA.x + biaA.x; a[i][1] += gA.y + biaA.y;
        a[i][2] += gA.z + biaA.z; a[i][3] += gA.w + biaA.w;
        a[i][4] += gB.x + biaB.x; a[i][5] += gB.y + biaB.y;
        a[i][6] += gB.z + biaB.z; a[i][7] += gB.w + biaB.w;
        float s1 = ((a[i][0] + a[i][1]) + (a[i][2] + a[i][3]))
                 + ((a[i][4] + a[i][5]) + (a[i][6] + a[i][7]));
        float s2 = ((a[i][0] * a[i][0] + a[i][1] * a[i][1]) + (a[i][2] * a[i][2] + a[i][3] * a[i][3]))
                 + ((a[i][4] * a[i][4] + a[i][5] * a[i][5]) + (a[i][6] * a[i][6] + a[i][7] * a[i][7]));
        s1 += __shfl_xor_sync(0xffffffffu, s1, 1);
        s2 += __shfl_xor_sync(0xffffffffu, s2, 1);
        s1 += __shfl_xor_sync(0xffffffffu, s1, 2);
        s2 += __shfl_xor_sync(0xffffffffu, s2, 2);
        s1p[i] = s1; s2p[i] = s2;
    }
    if ((l & 3) == 0) {
#pragma unroll
        for (int i = 0; i < 4; i++)
            *(float2*)&sred[(r0 + i) * 4 + (w_ & 1) * 2] = make_float2(s1p[i], s2p[i]);
    }
    __syncthreads();

    float4 gvA = *(const float4*)&gam[c0];
    float4 gvB = *(const float4*)&gam[c0 + 4];
    float4 beA = *(const float4*)&bet[c0];
    float4 beB = *(const float4*)&bet[c0 + 4];
    float csq[8];
#pragma unroll
    for (int j = 0; j < 8; j++) csq[j] = 0.f;

#pragma unroll
    for (int i = 0; i < 4; i++) {
        int rg = base + r0 + i;
        int ci = cats[r0 + i];
        float4 sr = *(const float4*)&sred[(r0 + i) * 4];
        float s1 = sr.x + sr.z, s2 = sr.y + sr.w;
        float mean = s1 * (1.f / 64.f);
        float var  = s2 * (1.f / 64.f) - mean * mean;
        float rs   = rsqrtf(var + 1e-5f);
        float h0 = fmaxf(fmaf((a[i][0] - mean) * rs, gvA.x, beA.x), 0.f);
        float h1 = fmaxf(fmaf((a[i][1] - mean) * rs, gvA.y, beA.y), 0.f);
        float h2 = fmaxf(fmaf((a[i][2] - mean) * rs, gvA.z, beA.z), 0.f);
        float h3 = fmaxf(fmaf((a[i][3] - mean) * rs, gvA.w, beA.w), 0.f);
        float h4 = fmaxf(fmaf((a[i][4] - mean) * rs, gvB.x, beB.x), 0.f);
        float h5 = fmaxf(fmaf((a[i][5] - mean) * rs, gvB.y, beB.y), 0.f);
        float h6 = fmaxf(fmaf((a[i][6] - mean) * rs, gvB.z, beB.z), 0.f);
        float h7 = fmaxf(fmaf((a[i][7] - mean) * rs, gvB.w, beB.w), 0.f);
        if (rg < N) {
            float4* hp = (float4*)&g_H[(size_t)rg * 64 + c0];
            __stcs(hp,     make_float4(h0, h1, h2, h3));
            __stcs(hp + 1, make_float4(h4, h5, h6, h7));
            float* ap = aggOut + (size_t)ci * 64 + c0;
            float4 curA = *(const float4*)ap;
            float4 curB = *(const float4*)(ap + 4);
            agg_max(ap + 0, h0, curA.x);
            agg_max(ap + 1, h1, curA.y);
            agg_max(ap + 2, h2, curA.z);
            agg_max(ap + 3, h3, curA.w);
            agg_max(ap + 4, h4, curB.x);
            agg_max(ap + 5, h5, curB.y);
            agg_max(ap + 6, h6, curB.z);
            agg_max(ap + 7, h7, curB.w);
            if (COLSQ) {
                csq[0] = fmaf(h0, h0, csq[0]); csq[1] = fmaf(h1, h1, csq[1]);
                csq[2] = fmaf(h2, h2, csq[2]); csq[3] = fmaf(h3, h3, csq[3]);
                csq[4] = fmaf(h4, h4, csq[4]); csq[5] = fmaf(h5, h5, csq[5]);
                csq[6] = fmaf(h6, h6, csq[6]); csq[7] = fmaf(h7, h7, csq[7]);
            }
        }
    }
    if (COLSQ) {
        if (tid < 64) scolsq[tid] = 0.f;
        __syncthreads();
#pragma unroll
        for (int j = 0; j < 8; j++) atomicAdd(&scolsq[c0 + j], csq[j]);
        __syncthreads();
        if (tid < 64) atomicAdd(&g_colsq[tid], scolsq[tid]);
    }
}

// colsq for agg half: sum_s count[s] * agg2[s,j]^2  (L2-hot)
__global__ void k_aggsq(int aggIdx) {
    const float* agg = g_agg + (size_t)aggIdx * NSEG * 64;
    int j = threadIdx.x & 63;
    int sb_ = threadIdx.x >> 6;
    float acc = 0.f;
    for (int s = blockIdx.x * 4 + sb_; s < NSEG; s += gridDim.x * 4) {
        float cnt = (float)g_cnt[s];
        if (cnt > 0.f) {
            float v = agg[(size_t)s * 64 + j];
            acc = fmaf(cnt, v * v, acc);
        }
    }
    __shared__ float red[64];
    if (threadIdx.x < 64) red[threadIdx.x] = 0.f;
    __syncthreads();
    atomicAdd(&red[j], acc);
    __syncthreads();
    if (threadIdx.x < 64) atomicAdd(&g_colsq[64 + threadIdx.x], red[threadIdx.x]);
}

__global__ void k_inv() {
    int j = threadIdx.x;
    if (j < 128) g_inv[j] = 1.f / (sqrtf(g_colsq[j]) + 1e-12f);
}

// out[i] = [h2 | agg2[cat]] * inv_norm  — coalesced, MLP=4:
// warp = 4 rows (lane = one float4 chunk of each); batch cat loads,
// then 4 independent value loads, then 4 stores.
__global__ __launch_bounds__(256) void k_scale(
    const void* __restrict__ cat, int aggIdx, float* __restrict__ out, int N)
{
    int gwarp = (blockIdx.x * 256 + threadIdx.x) >> 5;
    int c4 = threadIdx.x & 31;
    int row0 = gwarp * 4;
    if (row0 >= N) return;
    int is64 = g_is64;
    const float* agg = g_agg + (size_t)aggIdx * NSEG * 64;
    float4 iv = ((const float4*)g_inv)[c4];

    int cs[4];
#pragma unroll
    for (int i = 0; i < 4; i++) {
        int r = row0 + i;
        cs[i] = (c4 >= 16 && r < N) ? get_cat(cat, r, is64) : 0;
    }
    float4 v[4];
#pragma unroll
    for (int i = 0; i < 4; i++) {
        int r = row0 + i;
        if (r < N) {
            if (c4 < 16) v[i] = __ldcs(((const float4*)&g_H[(size_t)r * 64]) + c4);
            else         v[i] = ((const float4*)&agg[(size_t)cs[i] * 64])[c4 - 16];
        }
    }
#pragma unroll
    for (int i = 0; i < 4; i++) {
        int r = row0 + i;
        if (r < N)
            __stcs(((float4*)&out[(size_t)r * 128]) + c4,
                   make_float4(v[i].x * iv.x, v[i].y * iv.y, v[i].z * iv.z, v[i].w * iv.w));
    }
}

// ---------------- launch ----------------
extern "C" void kernel_launch(void* const* d_in, const int* in_sizes, int n_in,
                              void* d_out, int out_size)
{
    const float* x  = (const float*)d_in[0];
    const void*  cat = d_in[1];
    int wb = (in_sizes[2] == 1) ? 3 : 2;
    const float* W0 = (const float*)d_in[wb + 0];
    const float* b0 = (const float*)d_in[wb + 1];
    const float* g0 = (const float*)d_in[wb + 2];
    const float* e0 = (const float*)d_in[wb + 3];
    const float* W1 = (const float*)d_in[wb + 4];
    const float* b1 = (const float*)d_in[wb + 5];
    const float* g1 = (const float*)d_in[wb + 6];
    const float* e1 = (const float*)d_in[wb + 7];
    const float* W2 = (const float*)d_in[wb + 8];
    const float* b2 = (const float*)d_in[wb + 9];
    const float* g2 = (const float*)d_in[wb + 10];
    const float* e2 = (const float*)d_in[wb + 11];

    int N = in_sizes[0] / 8;
    float* out = (float*)d_out;

    cudaFuncSetAttribute(k_layer0, cudaFuncAttributeMaxDynamicSharedMemorySize, L0_SMEM);
    cudaFuncSetAttribute(k_aggmm, cudaFuncAttributeMaxDynamicSharedMemorySize, AMM_SMEM);
    cudaFuncSetAttribute(k_layer<false>, cudaFuncAttributeMaxDynamicSharedMemorySize, SMEM_BYTES);
    cudaFuncSetAttribute(k_layer<true>,  cudaFuncAttributeMaxDynamicSharedMemorySize, SMEM_BYTES);

    int nblk = (N + 127) / 128;
    int nblk_s = (NSEG + 127) / 128;

    k_init<<<8192, 256>>>((const unsigned int*)cat);                 // launch 1
    k_layer0<<<nblk, 256, L0_SMEM>>>(x, cat, W0, b0, g0, e0, N);     // launch 2

    // layer 1: G = agg0 @ W1_bot ; then rows
    k_aggmm<<<nblk_s, 256, AMM_SMEM>>>(0, W1 + 64 * 64);             // launch 3
    k_layer<false><<<nblk, 256, SMEM_BYTES>>>(cat, 1, W1, b1, g1, e1, N);  // launch 4 <- ncu

    // layer 2
    k_aggmm<<<nblk_s, 256, AMM_SMEM>>>(1, W2 + 64 * 64);
    k_layer<true ><<<nblk, 256, SMEM_BYTES>>>(cat, 2, W2, b2, g2, e2, N);

    k_aggsq<<<512, 256>>>(2);
    k_inv<<<1, 128>>>();
    // warps = ceil(N/4); 8 warps per block
    int sc_blocks = (int)((((long long)N + 3) / 4 + 7) / 8);
    k_scale<<<sc_blocks, 256>>>(cat, 2, out, N);
}

// round 15
// speedup vs baseline: 1.4004x; 1.0031x over previous
#include <cuda_runtime.h>
#include <cstdint>

// ---------------- static scratch (allocation-free rule) ----------------
#define NSEG 100000
#define NROWS_MAX 2000000

__device__ __align__(16) float g_H[(size_t)NROWS_MAX * 64];      // 512 MB (streaming)
__device__ __align__(16) float g_agg[3u * NSEG * 64];            // 76.8 MB (L2-hot)
__device__ __align__(16) float g_G[(size_t)NSEG * 64];           // 25.6 MB (L2-hot)
__device__ int   g_cnt[NSEG];
__device__ float g_colsq[128];
__device__ float g_inv[128];
__device__ int   g_is64;

// ---------------- f32x2 packed-math helpers (sm_103a) ----------------
__device__ __forceinline__ unsigned long long pack2(float a, float b) {
    unsigned long long r;
    asm("mov.b64 %0, {%1, %2};" : "=l"(r) : "f"(a), "f"(b));
    return r;
}
__device__ __forceinline__ unsigned long long ffma2(unsigned long long a,
                                                    unsigned long long b,
                                                    unsigned long long c) {
    unsigned long long d;
    asm("fma.rn.f32x2 %0, %1, %2, %3;" : "=l"(d) : "l"(a), "l"(b), "l"(c));
    return d;
}
__device__ __forceinline__ void unpack2(unsigned long long v, float& a, float& b) {
    asm("mov.b64 {%0, %1}, %2;" : "=f"(a), "=f"(b) : "l"(v));
}

__device__ __forceinline__ int get_cat(const void* cat, int i, int is64) {
    if (is64) return (int)((const long long*)cat)[i];
    return ((const int*)cat)[i];
}

// filtered float atomicMax for non-negative floats (uint monotone)
__device__ __forceinline__ void agg_max(float* p, float h, float cur) {
    if (h > cur) atomicMax((unsigned int*)p, __float_as_uint(h));
}

// ---------------- kernels ----------------

// init + dtype detect fused (keeps k_layer<false> at launch index 4 for ncu)
__global__ void k_init(const unsigned int* cat) {
    int i = blockIdx.x * blockDim.x + threadIdx.x;
    if (blockIdx.x == 0 && threadIdx.x == 0) {
        int is64 = 1;
        for (int t = 0; t < 64; t++)
            if (cat[2 * t + 1] != 0u) { is64 = 0; break; }
        g_is64 = is64;
    }
    int stride = gridDim.x * blockDim.x;
    float4 z = make_float4(0.f, 0.f, 0.f, 0.f);
    float4* a4 = (float4*)g_agg;
    const int T4 = 3 * NSEG * 64 / 4;
    for (int j = i; j < T4; j += stride) a4[j] = z;
    for (int j = i; j < NSEG; j += stride) g_cnt[j] = 0;
    if (i < 128) g_colsq[i] = 0.f;
}

// ---------------- Layer 0 (tiled, low-reg, 4 CTAs/SM) ----------------
#define L0_XS_BYTES (128 * 8 * 4)        // 4096
#define L0_WS_BYTES (8 * 64 * 4)         // 2048
#define L0_CATS_OFF (L0_XS_BYTES + L0_WS_BYTES)
#define L0_SMEM     (L0_CATS_OFF + 512)

__global__ __launch_bounds__(256, 4) void k_layer0(
    const float* __restrict__ x, const void* __restrict__ cat,
    const float* __restrict__ W, const float* __restrict__ bia,
    const float* __restrict__ gam, const float* __restrict__ bet, int N)
{
    extern __shared__ char smem[];
    float* Xs = (float*)smem;                                   // [128][8]
    const ulonglong2* Wsp = (const ulonglong2*)(smem + L0_XS_BYTES); // [8][16]
    int* cats = (int*)(smem + L0_CATS_OFF);

    int tid = threadIdx.x;
    int base = blockIdx.x * 128;
    int is64 = g_is64;

    if (tid < 128) {
        int r = base + tid;
        int c = (r < N) ? get_cat(cat, r, is64) : 0;
        cats[tid] = c;
        if (r < N) atomicAdd(&g_cnt[c], 1);
    }
    if (tid < 128) {
        ((float4*)(smem + L0_XS_BYTES))[tid] = ((const float4*)W)[tid];
    }
    {
        int r = tid >> 1, c4 = tid & 1;
        int rg = base + r;
        float4 v = make_float4(0.f, 0.f, 0.f, 0.f);
        if (rg < N) v = __ldcs(((const float4*)x) + (size_t)rg * 2 + c4);  // streaming
        ((float4*)Xs)[tid] = v;
    }
    __syncthreads();

    int tx = tid & 15, tyg = tid >> 4;
    int r0 = tyg * 8;

    unsigned long long acc[8][2];
#pragma unroll
    for (int i = 0; i < 8; i++) { acc[i][0] = 0ull; acc[i][1] = 0ull; }

#pragma unroll
    for (int k4 = 0; k4 < 2; k4++) {
        ulonglong2 w0 = Wsp[(k4 * 4 + 0) * 16 + tx];
        ulonglong2 w1 = Wsp[(k4 * 4 + 1) * 16 + tx];
        ulonglong2 w2 = Wsp[(k4 * 4 + 2) * 16 + tx];
        ulonglong2 w3 = Wsp[(k4 * 4 + 3) * 16 + tx];
#pragma unroll
        for (int i = 0; i < 8; i++) {
            float4 xv = ((const float4*)(Xs + (r0 + i) * 8))[k4];
            unsigned long long d;
            d = pack2(xv.x, xv.x);
            acc[i][0] = ffma2(d, w0.x, acc[i][0]); acc[i][1] = ffma2(d, w0.y, acc[i][1]);
            d = pack2(xv.y, xv.y);
            acc[i][0] = ffma2(d, w1.x, acc[i][0]); acc[i][1] = ffma2(d, w1.y, acc[i][1]);
            d = pack2(xv.z, xv.z);
            acc[i][0] = ffma2(d, w2.x, acc[i][0]); acc[i][1] = ffma2(d, w2.y, acc[i][1]);
            d = pack2(xv.w, xv.w);
            acc[i][0] = ffma2(d, w3.x, acc[i][0]); acc[i][1] = ffma2(d, w3.y, acc[i][1]);
        }
    }

    int c0 = tx * 4;
    float4 bv  = *(const float4*)&bia[c0];
    float4 gv  = *(const float4*)&gam[c0];
    float4 bev = *(const float4*)&bet[c0];

    float* agg0 = g_agg;

#pragma unroll
    for (int i = 0; i < 8; i++) {
        int rg = base + r0 + i;
        int ci = cats[r0 + i];
        float4 cur = *(const float4*)(agg0 + (size_t)ci * 64 + c0);
        float a0, a1, a2, a3;
        unpack2(acc[i][0], a0, a1);
        unpack2(acc[i][1], a2, a3);
        a0 += bv.x; a1 += bv.y; a2 += bv.z; a3 += bv.w;
        float s1 = a0 + a1 + a2 + a3;
        float s2 = a0 * a0 + a1 * a1 + a2 * a2 + a3 * a3;
#pragma unroll
        for (int m = 1; m < 16; m <<= 1) {
            s1 += __shfl_xor_sync(0xffffffffu, s1, m);
            s2 += __shfl_xor_sync(0xffffffffu, s2, m);
        }
        float mean = s1 * (1.f / 64.f);
        float var  = s2 * (1.f / 64.f) - mean * mean;
        float rs   = rsqrtf(var + 1e-5f);
        float h0 = fmaxf(fmaf((a0 - mean) * rs, gv.x, bev.x), 0.f);
        float h1 = fmaxf(fmaf((a1 - mean) * rs, gv.y, bev.y), 0.f);
        float h2 = fmaxf(fmaf((a2 - mean) * rs, gv.z, bev.z), 0.f);
        float h3 = fmaxf(fmaf((a3 - mean) * rs, gv.w, bev.w), 0.f);
        if (rg < N) {
            __stcs(((float4*)&g_H[(size_t)rg * 64]) + tx, make_float4(h0, h1, h2, h3));
            float* ap = agg0 + (size_t)ci * 64 + c0;
            agg_max(ap + 0, h0, cur.x);
            agg_max(ap + 1, h1, cur.y);
            agg_max(ap + 2, h2, cur.z);
            agg_max(ap + 3, h3, cur.w);
        }
    }
}

// ---------------- G = agg @ W_bot  (per-segment precompute) ----------------
#define AMM_SMEM (128 * 64 * 4 + 64 * 64 * 4)   // 49152

__global__ __launch_bounds__(256, 3) void k_aggmm(int aggInIdx, const float* __restrict__ Wbot)
{
    extern __shared__ char smem[];
    float* As = (float*)smem;
    const ulonglong2* Wsp = (const ulonglong2*)(smem + 128 * 64 * 4);
    const float* agg = g_agg + (size_t)aggInIdx * NSEG * 64;

    int tid = threadIdx.x;
    int base = blockIdx.x * 128;

    {
        const float4* Wv = (const float4*)Wbot;
        float4* Wd = (float4*)(smem + 128 * 64 * 4);
#pragma unroll
        for (int t = 0; t < 4; t++) Wd[tid + t * 256] = Wv[tid + t * 256];
    }
    {
#pragma unroll
        for (int t = 0; t < 8; t++) {
            int idx = tid + t * 256;
            int r = idx >> 4, c4 = idx & 15;
            int rg = base + r;
            float4 v = make_float4(0.f, 0.f, 0.f, 0.f);
            if (rg < NSEG) v = ((const float4*)&agg[(size_t)rg * 64])[c4];
            ((float4*)&As[r * 64])[c4] = v;
        }
    }
    __syncthreads();

    int tx = tid & 15, tyg = tid >> 4;
    int r0 = tyg * 8;

    unsigned long long acc[8][2];
#pragma unroll
    for (int i = 0; i < 8; i++) { acc[i][0] = 0ull; acc[i][1] = 0ull; }

#pragma unroll 4
    for (int k4 = 0; k4 < 16; k4++) {
        ulonglong2 w0 = Wsp[(k4 * 4 + 0) * 16 + tx];
        ulonglong2 w1 = Wsp[(k4 * 4 + 1) * 16 + tx];
        ulonglong2 w2 = Wsp[(k4 * 4 + 2) * 16 + tx];
        ulonglong2 w3 = Wsp[(k4 * 4 + 3) * 16 + tx];
#pragma unroll
        for (int i = 0; i < 8; i++) {
            float4 xv = ((const float4*)(As + (r0 + i) * 64))[k4];
            unsigned long long d;
            d = pack2(xv.x, xv.x);
            acc[i][0] = ffma2(d, w0.x, acc[i][0]); acc[i][1] = ffma2(d, w0.y, acc[i][1]);
            d = pack2(xv.y, xv.y);
            acc[i][0] = ffma2(d, w1.x, acc[i][0]); acc[i][1] = ffma2(d, w1.y, acc[i][1]);
            d = pack2(xv.z, xv.z);
            acc[i][0] = ffma2(d, w2.x, acc[i][0]); acc[i][1] = ffma2(d, w2.y, acc[i][1]);
            d = pack2(xv.w, xv.w);
            acc[i][0] = ffma2(d, w3.x, acc[i][0]); acc[i][1] = ffma2(d, w3.y, acc[i][1]);
        }
    }

    int c0 = tx * 4;
#pragma unroll
    for (int i = 0; i < 8; i++) {
        int rg = base + r0 + i;
        if (rg < NSEG) {
            float a0, a1, a2, a3;
            unpack2(acc[i][0], a0, a1);
            unpack2(acc[i][1], a2, a3);
            *(float4*)&g_G[(size_t)rg * 64 + c0] = make_float4(a0, a1, a2, a3);
        }
    }
}

// ---------------- Layers 1/2 (balanced warp tile, cur-load pipeline) -------
#define XS_BYTES  (128 * 64 * 4)                 // 32768
#define WS_BYTES  (64 * 64 * 4)                  // 16384
#define CATS_OFF  (XS_BYTES + WS_BYTES)          // 49152
#define SRED_OFF  (CATS_OFF + 512)               // 49664
#define SCSQ_OFF  (SRED_OFF + 128 * 16)          // 51712
#define SMEM_BYTES (SCSQ_OFF + 256)              // 51968

template <bool COLSQ>
__global__ __launch_bounds__(256, 3) void k_layer(
    const void* __restrict__ cat, int aggOutIdx,
    const float* __restrict__ Wtop, const float* __restrict__ bia,
    const float* __restrict__ gam, const float* __restrict__ bet, int N)
{
    extern __shared__ char smem[];
    float* Xs = (float*)smem;                                  // [128][64] swizzled
    const float* Ws = (const float*)(smem + XS_BYTES);         // [64][64]
    int* cats = (int*)(smem + CATS_OFF);
    float* sred = (float*)(smem + SRED_OFF);                   // [128][4]
    float* scolsq = (float*)(smem + SCSQ_OFF);

    float* aggOut = g_agg + (size_t)aggOutIdx * NSEG * 64;

    int tid = threadIdx.x;
    int base = blockIdx.x * 128;
    int is64 = g_is64;
    int w_ = tid >> 5, l = tid & 31;

    if (tid < 128) {
        int r = base + tid;
        cats[tid] = (r < N) ? get_cat(cat, r, is64) : 0;
    }
    {   // W_top: 1024 float4 (plain layout)
        const float4* Wv = (const float4*)Wtop;
        float4* Wd = (float4*)(smem + XS_BYTES);
#pragma unroll
        for (int t = 0; t < 4; t++) Wd[tid + t * 256] = Wv[tid + t * 256];
    }
    {   // Xs = H tile: 2048 float4, chunk-swizzled per row (streaming loads)
#pragma unroll
        for (int t = 0; t < 8; t++) {
            int idx = tid + t * 256;
            int r = idx >> 4, c4 = idx & 15;
            int rg = base + r;
            float4 v = make_float4(0.f, 0.f, 0.f, 0.f);
            if (rg < N) v = __ldcs(((const float4*)&g_H[(size_t)rg * 64]) + c4);
            ((float4*)Xs)[r * 16 + (c4 ^ ((r >> 2) & 7))] = v;
        }
    }
    __syncthreads();

    int txg = ((w_ & 1) << 2) | (l & 3);     // 0..7
    int tyg = ((w_ >> 1) << 3) | (l >> 2);   // 0..31
    int r0 = tyg * 4;
    int c0 = txg * 8;

    unsigned long long acc[4][4];
#pragma unroll
    for (int i = 0; i < 4; i++)
#pragma unroll
        for (int c = 0; c < 4; c++) acc[i][c] = 0ull;

#define K4BODY(J, X0, X1, X2, X3) { \
    const float* wrow = Ws + (k4 * 4 + (J)) * 64 + c0; \
    ulonglong2 wA = *(const ulonglong2*)wrow; \
    ulonglong2 wB = *(const ulonglong2*)(wrow + 4); \
    unsigned long long d; \
    d = pack2(X0, X0); \
    acc[0][0] = ffma2(d, wA.x, acc[0][0]); acc[0][1] = ffma2(d, wA.y, acc[0][1]); \
    acc[0][2] = ffma2(d, wB.x, acc[0][2]); acc[0][3] = ffma2(d, wB.y, acc[0][3]); \
    d = pack2(X1, X1); \
    acc[1][0] = ffma2(d, wA.x, acc[1][0]); acc[1][1] = ffma2(d, wA.y, acc[1][1]); \
    acc[1][2] = ffma2(d, wB.x, acc[1][2]); acc[1][3] = ffma2(d, wB.y, acc[1][3]); \
    d = pack2(X2, X2); \
    acc[2][0] = ffma2(d, wA.x, acc[2][0]); acc[2][1] = ffma2(d, wA.y, acc[2][1]); \
    acc[2][2] = ffma2(d, wB.x, acc[2][2]); acc[2][3] = ffma2(d, wB.y, acc[2][3]); \
    d = pack2(X3, X3); \
    acc[3][0] = ffma2(d, wA.x, acc[3][0]); acc[3][1] = ffma2(d, wA.y, acc[3][1]); \
    acc[3][2] = ffma2(d, wB.x, acc[3][2]); acc[3][3] = ffma2(d, wB.y, acc[3][3]); \
}

#pragma unroll 4
    for (int k4 = 0; k4 < 16; k4++) {
        int chunk = k4 ^ (tyg & 7);
        float4 xv0 = ((const float4*)Xs)[(r0 + 0) * 16 + chunk];
        float4 xv1 = ((const float4*)Xs)[(r0 + 1) * 16 + chunk];
        float4 xv2 = ((const float4*)Xs)[(r0 + 2) * 16 + chunk];
        float4 xv3 = ((const float4*)Xs)[(r0 + 3) * 16 + chunk];
        K4BODY(0, xv0.x, xv1.x, xv2.x, xv3.x)
        K4BODY(1, xv0.y, xv1.y, xv2.y, xv3.y)
        K4BODY(2, xv0.z, xv1.z, xv2.z, xv3.z)
        K4BODY(3, xv0.w, xv1.w, xv2.w, xv3.w)
    }
#undef K4BODY

    // ---- epilogue ----
    float4 biaA = *(const float4*)&bia[c0];
    float4 biaB = *(const float4*)&bia[c0 + 4];

    float a[4][8];
    float s1p[4], s2p[4];
#pragma unroll
    for (int i = 0; i < 4; i++) {
        int ci = cats[r0 + i];
        const float* gp = &g_G[(size_t)ci * 64 + c0];
        float4 gA = *(const float4*)gp;
        float4 gB = *(const float4*)(gp + 4);
        unpack2(acc[i][0], a[i][0], a[i][1]);
        unpack2(acc[i][1], a[i][2], a[i][3]);
        unpack2(acc[i][2], a[i][4], a[i][5]);
        unpack2(acc[i][3], a[i][6], a[i][7]);
        a[i][0] += gA.x + biaA.x; a[i][1] += gA.y + biaA.y;
        a[i][2] += gA.z + biaA.z; a[i][3] += gA.w + biaA.w;
        a[i][4] += gB.x + biaB.x; a[i][5] += gB.y + biaB.y;
        a[i][6] += gB.z + biaB.z; a[i][7] += gB.w + biaB.w;
        float s1 = ((a[i][0] + a[i][1]) + (a[i][2] + a[i][3]))
                 + ((a[i][4] + a[i][5]) + (a[i][6] + a[i][7]));
        float s2 = ((a[i][0] * a[i][0] + a[i][1] * a[i][1]) + (a[i][2] * a[i][2] + a[i][3] * a[i][3]))
                 + ((a[i][4] * a[i][4] + a[i][5] * a[i][5]) + (a[i][6] * a[i][6] + a[i][7] * a[i][7]));
        s1 += __shfl_xor_sync(0xffffffffu, s1, 1);
        s2 += __shfl_xor_sync(0xffffffffu, s2, 1);
        s1 += __shfl_xor_sync(0xffffffffu, s1, 2);
        s2 += __shfl_xor_sync(0xffffffffu, s2, 2);
        s1p[i] = s1; s2p[i] = s2;
    }
    if ((l & 3) == 0) {
#pragma unroll
        for (int i = 0; i < 4; i++)
            *(float2*)&sred[(r0 + i) * 4 + (w_ & 1) * 2] = make_float2(s1p[i], s2p[i]);
    }
    __syncthreads();

    float4 gvA = *(const float4*)&gam[c0];
    float4 gvB = *(const float4*)&gam[c0 + 4];
    float4 beA = *(const float4*)&bet[c0];
    float4 beB = *(const float4*)&bet[c0 + 4];
    float csq[8];
#pragma unroll
    for (int j = 0; j < 8; j++) csq[j] = 0.f;

    // cur-load software pipeline (depth 2): issue row i+1's filter loads
    // before row i's atomics so the L2 round-trip overlaps row processing.
    float4 curA, curB;
    {
        const float* ap0 = aggOut + (size_t)cats[r0] * 64 + c0;
        curA = *(const float4*)ap0;
        curB = *(const float4*)(ap0 + 4);
    }

#pragma unroll
    for (int i = 0; i < 4; i++) {
        float4 nA = curA, nB = curB;
        if (i < 3) {
            const float* apn = aggOut + (size_t)cats[r0 + i + 1] * 64 + c0;
            nA = *(const float4*)apn;
            nB = *(const float4*)(apn + 4);
        }
        int rg = base + r0 + i;
        int ci = cats[r0 + i];
        float4 sr = *(const float4*)&sred[(r0 + i) * 4];
        float s1 = sr.x + sr.z, s2 = sr.y + sr.w;
        float mean = s1 * (1.f / 64.f);
        float var  = s2 * (1.f / 64.f) - mean * mean;
        float rs   = rsqrtf(var + 1e-5f);
        float h0 = fmaxf(fmaf((a[i][0] - mean) * rs, gvA.x, beA.x), 0.f);
        float h1 = fmaxf(fmaf((a[i][1] - mean) * rs, gvA.y, beA.y), 0.f);
        float h2 = fmaxf(fmaf((a[i][2] - mean) * rs, gvA.z, beA.z), 0.f);
        float h3 = fmaxf(fmaf((a[i][3] - mean) * rs, gvA.w, beA.w), 0.f);
        float h4 = fmaxf(fmaf((a[i][4] - mean) * rs, gvB.x, beB.x), 0.f);
        float h5 = fmaxf(fmaf((a[i][5] - mean) * rs, gvB.y, beB.y), 0.f);
        float h6 = fmaxf(fmaf((a[i][6] - mean) * rs, gvB.z, beB.z), 0.f);
        float h7 = fmaxf(fmaf((a[i][7] - mean) * rs, gvB.w, beB.w), 0.f);
        if (rg < N) {
            float4* hp = (float4*)&g_H[(size_t)rg * 64 + c0];
            __stcs(hp,     make_float4(h0, h1, h2, h3));
            __stcs(hp + 1, make_float4(h4, h5, h6, h7));
            float* ap = aggOut + (size_t)ci * 64 + c0;
            agg_max(ap + 0, h0, curA.x);
            agg_max(ap + 1, h1, curA.y);
            agg_max(ap + 2, h2, curA.z);
            agg_max(ap + 3, h3, curA.w);
            agg_max(ap + 4, h4, curB.x);
            agg_max(ap + 5, h5, curB.y);
            agg_max(ap + 6, h6, curB.z);
            agg_max(ap + 7, h7, curB.w);
            if (COLSQ) {
                csq[0] = fmaf(h0, h0, csq[0]); csq[1] = fmaf(h1, h1, csq[1]);
                csq[2] = fmaf(h2, h2, csq[2]); csq[3] = fmaf(h3, h3, csq[3]);
                csq[4] = fmaf(h4, h4, csq[4]); csq[5] = fmaf(h5, h5, csq[5]);
                csq[6] = fmaf(h6, h6, csq[6]); csq[7] = fmaf(h7, h7, csq[7]);
            }
        }
        curA = nA; curB = nB;
    }
    if (COLSQ) {
        if (tid < 64) scolsq[tid] = 0.f;
        __syncthreads();
#pragma unroll
        for (int j = 0; j < 8; j++) atomicAdd(&scolsq[c0 + j], csq[j]);
        __syncthreads();
        if (tid < 64) atomicAdd(&g_colsq[tid], scolsq[tid]);
    }
}

// colsq for agg half: sum_s count[s] * agg2[s,j]^2  (L2-hot)
__global__ void k_aggsq(int aggIdx) {
    const float* agg = g_agg + (size_t)aggIdx * NSEG * 64;
    int j = threadIdx.x & 63;
    int sb_ = threadIdx.x >> 6;
    float acc = 0.f;
    for (int s = blockIdx.x * 4 + sb_; s < NSEG; s += gridDim.x * 4) {
        float cnt = (float)g_cnt[s];
        if (cnt > 0.f) {
            float v = agg[(size_t)s * 64 + j];
            acc = fmaf(cnt, v * v, acc);
        }
    }
    __shared__ float red[64];
    if (threadIdx.x < 64) red[threadIdx.x] = 0.f;
    __syncthreads();
    atomicAdd(&red[j], acc);
    __syncthreads();
    if (threadIdx.x < 64) atomicAdd(&g_colsq[64 + threadIdx.x], red[threadIdx.x]);
}

__global__ void k_inv() {
    int j = threadIdx.x;
    if (j < 128) g_inv[j] = 1.f / (sqrtf(g_colsq[j]) + 1e-12f);
}

// out[i] = [h2 | agg2[cat]] * inv_norm  — coalesced, MLP=8:
// warp = 8 rows (lane = one float4 chunk of each); batch cat loads,
// then 8 independent value loads, then 8 stores.
__global__ __launch_bounds__(256) void k_scale(
    const void* __restrict__ cat, int aggIdx, float* __restrict__ out, int N)
{
    int gwarp = (blockIdx.x * 256 + threadIdx.x) >> 5;
    int c4 = threadIdx.x & 31;
    int row0 = gwarp * 8;
    if (row0 >= N) return;
    int is64 = g_is64;
    const float* agg = g_agg + (size_t)aggIdx * NSEG * 64;
    float4 iv = ((const float4*)g_inv)[c4];

    int cs[8];
#pragma unroll
    for (int i = 0; i < 8; i++) {
        int r = row0 + i;
        cs[i] = (c4 >= 16 && r < N) ? get_cat(cat, r, is64) : 0;
    }
    float4 v[8];
#pragma unroll
    for (int i = 0; i < 8; i++) {
        int r = row0 + i;
        if (r < N) {
            if (c4 < 16) v[i] = __ldcs(((const float4*)&g_H[(size_t)r * 64]) + c4);
            else         v[i] = ((const float4*)&agg[(size_t)cs[i] * 64])[c4 - 16];
        }
    }
#pragma unroll
    for (int i = 0; i < 8; i++) {
        int r = row0 + i;
        if (r < N)
            __stcs(((float4*)&out[(size_t)r * 128]) + c4,
                   make_float4(v[i].x * iv.x, v[i].y * iv.y, v[i].z * iv.z, v[i].w * iv.w));
    }
}

// ---------------- launch ----------------
extern "C" void kernel_launch(void* const* d_in, const int* in_sizes, int n_in,
                              void* d_out, int out_size)
{
    const float* x  = (const float*)d_in[0];
    const void*  cat = d_in[1];
    int wb = (in_sizes[2] == 1) ? 3 : 2;
    const float* W0 = (const float*)d_in[wb + 0];
    const float* b0 = (const float*)d_in[wb + 1];
    const float* g0 = (const float*)d_in[wb + 2];
    const float* e0 = (const float*)d_in[wb + 3];
    const float* W1 = (const float*)d_in[wb + 4];
    const float* b1 = (const float*)d_in[wb + 5];
    const float* g1 = (const float*)d_in[wb + 6];
    const float* e1 = (const float*)d_in[wb + 7];
    const float* W2 = (const float*)d_in[wb + 8];
    const float* b2 = (const float*)d_in[wb + 9];
    const float* g2 = (const float*)d_in[wb + 10];
    const float* e2 = (const float*)d_in[wb + 11];

    int N = in_sizes[0] / 8;
    float* out = (float*)d_out;

    cudaFuncSetAttribute(k_layer0, cudaFuncAttributeMaxDynamicSharedMemorySize, L0_SMEM);
    cudaFuncSetAttribute(k_aggmm, cudaFuncAttributeMaxDynamicSharedMemorySize, AMM_SMEM);
    cudaFuncSetAttribute(k_layer<false>, cudaFuncAttributeMaxDynamicSharedMemorySize, SMEM_BYTES);
    cudaFuncSetAttribute(k_layer<true>,  cudaFuncAttributeMaxDynamicSharedMemorySize, SMEM_BYTES);

    int nblk = (N + 127) / 128;
    int nblk_s = (NSEG + 127) / 128;

    k_init<<<8192, 256>>>((const unsigned int*)cat);                 // launch 1
    k_layer0<<<nblk, 256, L0_SMEM>>>(x, cat, W0, b0, g0, e0, N);     // launch 2

    // layer 1: G = agg0 @ W1_bot ; then rows
    k_aggmm<<<nblk_s, 256, AMM_SMEM>>>(0, W1 + 64 * 64);             // launch 3
    k_layer<false><<<nblk, 256, SMEM_BYTES>>>(cat, 1, W1, b1, g1, e1, N);  // launch 4 <- ncu

    // layer 2
    k_aggmm<<<nblk_s, 256, AMM_SMEM>>>(1, W2 + 64 * 64);
    k_layer<true ><<<nblk, 256, SMEM_BYTES>>>(cat, 2, W2, b2, g2, e2, N);

    k_aggsq<<<512, 256>>>(2);
    k_inv<<<1, 128>>>();
    // warps = ceil(N/8); 8 warps per block
    int sc_blocks = (int)((((long long)N + 7) / 8 + 7) / 8);
    k_scale<<<sc_blocks, 256>>>(cat, 2, out, N);
}